// round 1
// baseline (speedup 1.0000x reference)
#include <cuda_runtime.h>
#include <math.h>

#define NROW 8192
#define DIM 1024
#define DIM2 512
#define BM 128
#define BN 128
#define BK 8
#define NCHUNK 16
#define CHUNK_COLS 512            // 4 col tiles of 128
#define NUNITS ((NROW / BM) * NCHUNK)  // 64 * 16 = 1024
#define BIGF 9999999.0f
#define MARGINF 0.3f

// ---------------- scratch (no cudaMalloc allowed) ----------------
__device__ int   g_lab64;
__device__ float g_sq[NROW];
__device__ float g_nrm[NROW];
__device__ float g_p1v[NCHUNK][NROW];
__device__ float g_p2v[NCHUNK][NROW];
__device__ int   g_p1i[NCHUNK][NROW];
__device__ int   g_p2i[NCHUNK][NROW];
__device__ float g_pmn[NCHUNK][NROW];
__device__ float g_ap1[NROW], g_ap2[NROW], g_an[NROW];
__device__ int   g_j1[NROW], g_j2[NROW];
__device__ float g_a1[NROW], g_a2[NROW];

__device__ __forceinline__ int getlab(const void* lab, int i, int is64) {
    if (is64) return (int)((const long long*)lab)[i];
    return ((const int*)lab)[i];
}

// key ordering replicating jax top_k: larger value wins; tie -> smaller index
__device__ __forceinline__ bool keybetter(float av, int ai, float bv, int bi) {
    return (av > bv) || (av == bv && ai < bi);
}

// ---------------- kernel 0: detect label dtype width ----------------
__global__ void k_detect(const void* lab) {
    const unsigned* p = (const unsigned*)lab;
    int is64 = 1;
    for (int i = 0; i < 64; i++) {
        if (p[2 * i + 1] != 0u) { is64 = 0; break; }
    }
    g_lab64 = is64;
}

// ---------------- kernel 1: row norms ----------------
__global__ void k_norms(const float* __restrict__ emb, const float* __restrict__ clot) {
    int r = blockIdx.x, t = threadIdx.x;
    float4 v = ((const float4*)(emb + (size_t)r * DIM))[t];   // 256 threads * 4 = 1024
    float s = v.x * v.x + v.y * v.y + v.z * v.z + v.w * v.w;
    float c = 0.f;
    if (t < DIM2 / 4) {
        float4 w = ((const float4*)(clot + (size_t)r * DIM2))[t];
        c = w.x * w.x + w.y * w.y + w.z * w.z + w.w * w.w;
    }
    __shared__ float se[256], sc[256];
    se[t] = s; sc[t] = c;
    __syncthreads();
    for (int o = 128; o > 0; o >>= 1) {
        if (t < o) { se[t] += se[t + o]; sc[t] += sc[t + o]; }
        __syncthreads();
    }
    if (t == 0) { g_sq[r] = se[0]; g_nrm[r] = sqrtf(sc[0]); }
}

// ---------------- kernel 2: fused dist GEMM + top2/min stats ----------------
__global__ __launch_bounds__(256, 1)
void k_dist(const float* __restrict__ emb, const void* __restrict__ lab) {
    const int lab64 = g_lab64;
    __shared__ float As[BK][BM + 4];   // K-major, pad 4 -> row stride 132 (528B, 16B aligned)
    __shared__ float Bs[BK][BN + 4];
    __shared__ float sqj[BN];
    __shared__ int   labj[BN];

    const int tid = threadIdx.x;
    const int tx = tid & 15, ty = tid >> 4;
    const int lrow = tid >> 1;          // 0..127
    const int lk   = (tid & 1) * 4;     // 0 or 4

    for (int u = blockIdx.x; u < NUNITS; u += gridDim.x) {
        const int rb = u >> 4;
        const int chunk = u & (NCHUNK - 1);
        const int r0 = rb * BM;

        float sqi[8]; int labi[8];
        #pragma unroll
        for (int i = 0; i < 8; i++) {
            int rr = r0 + ty * 8 + i;
            sqi[i] = g_sq[rr];
            labi[i] = getlab(lab, rr, lab64);
        }
        float b1v[8], b2v[8], mn[8]; int b1i[8], b2i[8];
        #pragma unroll
        for (int i = 0; i < 8; i++) {
            b1v[i] = -INFINITY; b2v[i] = -INFINITY; mn[i] = INFINITY;
            b1i[i] = 0x7fffffff; b2i[i] = 0x7fffffff;
        }

        for (int ct = 0; ct < 4; ct++) {
            const int c0 = chunk * CHUNK_COLS + ct * BN;
            __syncthreads();   // protect sqj/labj from previous epilogue readers
            if (tid < BN) {
                sqj[tid] = g_sq[c0 + tid];
                labj[tid] = getlab(lab, c0 + tid, lab64);
            }
            float acc[8][8];
            #pragma unroll
            for (int i = 0; i < 8; i++)
                #pragma unroll
                for (int j = 0; j < 8; j++) acc[i][j] = 0.f;

            for (int k0 = 0; k0 < DIM; k0 += BK) {
                float4 av = *(const float4*)(emb + (size_t)(r0 + lrow) * DIM + k0 + lk);
                float4 bv = *(const float4*)(emb + (size_t)(c0 + lrow) * DIM + k0 + lk);
                __syncthreads();   // previous tile compute done
                As[lk + 0][lrow] = av.x; As[lk + 1][lrow] = av.y;
                As[lk + 2][lrow] = av.z; As[lk + 3][lrow] = av.w;
                Bs[lk + 0][lrow] = bv.x; Bs[lk + 1][lrow] = bv.y;
                Bs[lk + 2][lrow] = bv.z; Bs[lk + 3][lrow] = bv.w;
                __syncthreads();
                #pragma unroll
                for (int k = 0; k < BK; k++) {
                    float a[8], b[8];
                    *(float4*)(a)     = *(const float4*)&As[k][ty * 8];
                    *(float4*)(a + 4) = *(const float4*)&As[k][ty * 8 + 4];
                    *(float4*)(b)     = *(const float4*)&Bs[k][tx * 8];
                    *(float4*)(b + 4) = *(const float4*)&Bs[k][tx * 8 + 4];
                    #pragma unroll
                    for (int i = 0; i < 8; i++)
                        #pragma unroll
                        for (int j = 0; j < 8; j++)
                            acc[i][j] = fmaf(a[i], b[j], acc[i][j]);
                }
            }

            // epilogue: dist + masked top2 / min
            #pragma unroll
            for (int i = 0; i < 8; i++) {
                #pragma unroll
                for (int j = 0; j < 8; j++) {
                    const int jj = tx * 8 + j;
                    const int col = c0 + jj;
                    float d2 = sqi[i] + sqj[jj] - 2.0f * acc[i][j];
                    float dist = sqrtf(fmaxf(d2, 1e-12f));
                    bool same = (labi[i] == labj[jj]);
                    float pv = same ? dist : dist - BIGF;   // dist - BIG*(1-sim)
                    float nv = same ? dist + BIGF : dist;   // dist + BIG*sim
                    mn[i] = fminf(mn[i], nv);
                    if (keybetter(pv, col, b1v[i], b1i[i])) {
                        b2v[i] = b1v[i]; b2i[i] = b1i[i];
                        b1v[i] = pv;     b1i[i] = col;
                    } else if (keybetter(pv, col, b2v[i], b2i[i])) {
                        b2v[i] = pv; b2i[i] = col;
                    }
                }
            }
        }

        // merge across tx (16 lanes share each row-group); butterfly shuffles
        #pragma unroll
        for (int i = 0; i < 8; i++) {
            #pragma unroll
            for (int off = 8; off > 0; off >>= 1) {
                float o1v = __shfl_xor_sync(0xffffffffu, b1v[i], off);
                int   o1i = __shfl_xor_sync(0xffffffffu, b1i[i], off);
                float o2v = __shfl_xor_sync(0xffffffffu, b2v[i], off);
                int   o2i = __shfl_xor_sync(0xffffffffu, b2i[i], off);
                float omn = __shfl_xor_sync(0xffffffffu, mn[i],  off);
                mn[i] = fminf(mn[i], omn);
                if (keybetter(o1v, o1i, b1v[i], b1i[i])) {
                    if (keybetter(b1v[i], b1i[i], o2v, o2i)) { b2v[i] = b1v[i]; b2i[i] = b1i[i]; }
                    else                                     { b2v[i] = o2v;    b2i[i] = o2i;    }
                    b1v[i] = o1v; b1i[i] = o1i;
                } else if (keybetter(o1v, o1i, b2v[i], b2i[i])) {
                    b2v[i] = o1v; b2i[i] = o1i;
                }
            }
            if (tx == 0) {
                int rr = r0 + ty * 8 + i;
                g_p1v[chunk][rr] = b1v[i]; g_p1i[chunk][rr] = b1i[i];
                g_p2v[chunk][rr] = b2v[i]; g_p2i[chunk][rr] = b2i[i];
                g_pmn[chunk][rr] = mn[i];
            }
        }
    }
}

// ---------------- kernel 3: merge chunk partials per row ----------------
__global__ void k_merge() {
    int r = blockIdx.x * blockDim.x + threadIdx.x;
    if (r >= NROW) return;
    float b1v = -INFINITY, b2v = -INFINITY, mn = INFINITY;
    int b1i = 0x7fffffff, b2i = 0x7fffffff;
    for (int c = 0; c < NCHUNK; c++) {
        float o1v = g_p1v[c][r]; int o1i = g_p1i[c][r];
        float o2v = g_p2v[c][r]; int o2i = g_p2i[c][r];
        mn = fminf(mn, g_pmn[c][r]);
        if (keybetter(o1v, o1i, b1v, b1i)) {
            if (keybetter(b1v, b1i, o2v, o2i)) { b2v = b1v; b2i = b1i; }
            else                               { b2v = o2v; b2i = o2i; }
            b1v = o1v; b1i = o1i;
        } else if (keybetter(o1v, o1i, b2v, b2i)) {
            b2v = o1v; b2i = o1i;
        }
    }
    g_ap1[r] = b1v; g_ap2[r] = b2v;
    g_j1[r] = b1i;  g_j2[r] = b2i;
    g_an[r] = mn;
}

// ---------------- kernel 4: cos at the two selected positives ----------------
__global__ void k_alpha(const float* __restrict__ clot) {
    int w = threadIdx.x >> 5, lane = threadIdx.x & 31;
    int r = blockIdx.x * 8 + w;
    int j1 = g_j1[r], j2 = g_j2[r];
    const float* cr = clot + (size_t)r * DIM2;
    const float* ca = clot + (size_t)j1 * DIM2;
    const float* cb = clot + (size_t)j2 * DIM2;
    float d1 = 0.f, d2 = 0.f;
    for (int k = lane; k < DIM2; k += 32) {
        float c = cr[k];
        d1 = fmaf(c, ca[k], d1);
        d2 = fmaf(c, cb[k], d2);
    }
    for (int o = 16; o > 0; o >>= 1) {
        d1 += __shfl_xor_sync(0xffffffffu, d1, o);
        d2 += __shfl_xor_sync(0xffffffffu, d2, o);
    }
    if (lane == 0) {
        g_a1[r] = d1 / (g_nrm[r] * g_nrm[j1]);
        g_a2[r] = d2 / (g_nrm[r] * g_nrm[j2]);
    }
}

// ---------------- kernel 5: final loss reduction ----------------
__global__ void k_final(float* __restrict__ out) {
    int t = threadIdx.x;
    double s11 = 0.0, s13 = 0.0, sp = 0.0;
    for (int r = t; r < NROW; r += 1024) {
        float ap1 = g_ap1[r], ap2 = g_ap2[r], an = g_an[r];
        float a1 = g_a1[r], a2 = g_a2[r];
        float y  = (a1 < a2) ? -1.f : 1.f;
        float ym = (a1 == a2) ? 0.f : 1.f;
        float x1 = ap2 * ym;
        float x2 = ap1 * ym + MARGINF * (a1 - a2 - y);
        float t11 = fmaxf(0.f, -y * (x1 - x2) + MARGINF);
        float ap1m = ap1 + MARGINF * (a1 - 1.f);
        float t13 = fmaxf(0.f, -(an - ap1m) + MARGINF);
        s11 += (double)t11; s13 += (double)t13;
        sp += (an > ap1m) ? 1.0 : 0.0;
    }
    __shared__ double r1[1024], r2[1024], r3[1024];
    r1[t] = s11; r2[t] = s13; r3[t] = sp;
    __syncthreads();
    for (int o = 512; o > 0; o >>= 1) {
        if (t < o) { r1[t] += r1[t + o]; r2[t] += r2[t + o]; r3[t] += r3[t + o]; }
        __syncthreads();
    }
    if (t == 0) {
        out[0] = (float)(0.1 * (r1[0] / NROW) + (r2[0] / NROW));
        out[1] = (float)(r3[0] / NROW);
    }
}

// ---------------- launch ----------------
extern "C" void kernel_launch(void* const* d_in, const int* in_sizes, int n_in,
                              void* d_out, int out_size) {
    const float* emb  = (const float*)d_in[0];
    const void*  lab  = d_in[1];
    const float* clot = (const float*)d_in[2];
    float* out = (float*)d_out;

    k_detect<<<1, 1>>>(lab);
    k_norms<<<NROW, 256>>>(emb, clot);
    k_dist<<<148, 256>>>(emb, lab);
    k_merge<<<NROW / 256, 256>>>();
    k_alpha<<<NROW / 8, 256>>>(clot);
    k_final<<<1, 1024>>>(out);
}

// round 3
// speedup vs baseline: 3.5769x; 3.5769x over previous
#include <cuda_runtime.h>
#include <cuda_bf16.h>
#include <math.h>
#include <stdint.h>

#define NROW 8192
#define DIM 1024
#define DIM2 512
#define BM 128
#define BN 128
#define NCT (NROW / BN)            // 64 col-chunks
#define BIGF 9999999.0f
#define MARGINF 0.3f

#define STAGE_BYTES 16384          // A(128x64B) + B(128x64B): hi|lo packed per row
#define NSTG 4
#define SMEM_TOTAL (NSTG * STAGE_BYTES)   // 64 KB
#define NSTAGES_K 64               // 1024 / 16

// ---------------- device scratch ----------------
__device__ int   g_lab64;
__device__ float g_sq[NROW];
__device__ float g_nrm[NROW];
__device__ __nv_bfloat16 g_hi[(size_t)NROW * DIM];
__device__ __nv_bfloat16 g_lo[(size_t)NROW * DIM];
__device__ float g_p1v[NCT][NROW];
__device__ float g_p2v[NCT][NROW];
__device__ int   g_p1i[NCT][NROW];
__device__ int   g_p2i[NCT][NROW];
__device__ float g_pmn[NCT][NROW];
__device__ float g_ap1[NROW], g_ap2[NROW], g_an[NROW];
__device__ int   g_j1[NROW], g_j2[NROW];
__device__ float g_a1[NROW], g_a2[NROW];

// ---------------- helpers ----------------
__device__ __forceinline__ uint32_t smem_u32(const void* p) {
    uint32_t a;
    asm("{ .reg .u64 t; cvta.to.shared.u64 t, %1; cvt.u32.u64 %0, t; }" : "=r"(a) : "l"(p));
    return a;
}
__device__ __forceinline__ void cpasync16(uint32_t dst, const void* src) {
    asm volatile("cp.async.cg.shared.global [%0], [%1], 16;" :: "r"(dst), "l"(src));
}
#define CP_COMMIT() asm volatile("cp.async.commit_group;" ::: "memory")
#define CP_WAIT2()  asm volatile("cp.async.wait_group 2;" ::: "memory")
#define CP_WAIT0()  asm volatile("cp.async.wait_group 0;" ::: "memory")

#define LDM4(r, addr) \
    asm volatile("ldmatrix.sync.aligned.m8n8.x4.shared.b16 {%0,%1,%2,%3}, [%4];" \
        : "=r"((r)[0]), "=r"((r)[1]), "=r"((r)[2]), "=r"((r)[3]) : "r"(addr))

#define MMA16816(c, a, b0_, b1_) \
    asm volatile("mma.sync.aligned.m16n8k16.row.col.f32.bf16.bf16.f32 " \
        "{%0,%1,%2,%3}, {%4,%5,%6,%7}, {%8,%9}, {%0,%1,%2,%3};" \
        : "+f"((c)[0]), "+f"((c)[1]), "+f"((c)[2]), "+f"((c)[3]) \
        : "r"((a)[0]), "r"((a)[1]), "r"((a)[2]), "r"((a)[3]), "r"(b0_), "r"(b1_))

__device__ __forceinline__ int getlab(const void* lab, int i, int is64) {
    if (is64) return (int)((const long long*)lab)[i];
    return ((const int*)lab)[i];
}
__device__ __forceinline__ bool keybetter(float av, int ai, float bv, int bi) {
    return (av > bv) || (av == bv && ai < bi);
}
__device__ __forceinline__ uint32_t sw64(uint32_t off) { return off ^ ((off >> 3) & 0x30u); }

// ---------------- kernel 0: label width detect ----------------
__global__ void k_detect(const void* lab) {
    const unsigned* p = (const unsigned*)lab;
    int is64 = 1;
    for (int i = 0; i < 64; i++) if (p[2 * i + 1] != 0u) { is64 = 0; break; }
    g_lab64 = is64;
}

// ---------------- kernel 1: row norms ----------------
__global__ void k_norms(const float* __restrict__ emb, const float* __restrict__ clot) {
    int r = blockIdx.x, t = threadIdx.x;
    float4 v = ((const float4*)(emb + (size_t)r * DIM))[t];
    float s = v.x * v.x + v.y * v.y + v.z * v.z + v.w * v.w;
    float c = 0.f;
    if (t < DIM2 / 4) {
        float4 w = ((const float4*)(clot + (size_t)r * DIM2))[t];
        c = w.x * w.x + w.y * w.y + w.z * w.z + w.w * w.w;
    }
    __shared__ float se[256], sc[256];
    se[t] = s; sc[t] = c;
    __syncthreads();
    for (int o = 128; o > 0; o >>= 1) { if (t < o) { se[t] += se[t + o]; sc[t] += sc[t + o]; } __syncthreads(); }
    if (t == 0) { g_sq[r] = se[0]; g_nrm[r] = sqrtf(sc[0]); }
}

// ---------------- kernel 1b: split fp32 -> bf16 hi/lo ----------------
__global__ void k_split(const float* __restrict__ emb) {
    int r = blockIdx.x, t = threadIdx.x;
    float4 v = ((const float4*)(emb + (size_t)r * DIM))[t];
    float vv[4] = {v.x, v.y, v.z, v.w};
    __nv_bfloat16 h[4], l[4];
    #pragma unroll
    for (int i = 0; i < 4; i++) {
        h[i] = __float2bfloat16(vv[i]);
        l[i] = __float2bfloat16(vv[i] - __bfloat162float(h[i]));
    }
    size_t o = (size_t)r * DIM + t * 4;
    *(__nv_bfloat162*)(g_hi + o)     = __nv_bfloat162(h[0], h[1]);
    *(__nv_bfloat162*)(g_hi + o + 2) = __nv_bfloat162(h[2], h[3]);
    *(__nv_bfloat162*)(g_lo + o)     = __nv_bfloat162(l[0], l[1]);
    *(__nv_bfloat162*)(g_lo + o + 2) = __nv_bfloat162(l[2], l[3]);
}

// ---------------- kernel 2: HMMA split-bf16 GEMM + fused dist top2/min ----------------
// stage layout: A tile @0 (128 rows x 64B: segs 0-1 = hi k0..15, segs 2-3 = lo k0..15)
//               B tile @8192 (same for columns)
__global__ __launch_bounds__(256, 2) void k_dist_mma(const void* __restrict__ lab) {
    extern __shared__ char smem[];
    const uint32_t sb = smem_u32(smem);
    const int tid = threadIdx.x;
    const int lane = tid & 31, wid = tid >> 5;
    const int wm = wid >> 2, wn = wid & 3;
    const int r0 = blockIdx.y * BM, c0 = blockIdx.x * BN;
    const int lab64 = g_lab64;

    // ---- per-thread cp.async descriptors (4 x 16B per stage) ----
    const char* srcp[4];
    uint32_t dsto[4];
    #pragma unroll
    for (int u = 0; u < 4; u++) {
        int i = tid + u * 256;
        int tile = i >> 9;               // 0 = A, 1 = B
        int row = (i >> 2) & 127;
        int seg = i & 3;
        const __nv_bfloat16* sbase = (seg < 2) ? g_hi : g_lo;
        int grow = (tile ? c0 : r0) + row;
        srcp[u] = (const char*)(sbase + (size_t)grow * DIM + (seg & 1) * 8);
        dsto[u] = (uint32_t)tile * 8192u + sw64((uint32_t)row * 64u + (uint32_t)seg * 16u);
    }

    // ---- ldmatrix address offsets ----
    uint32_t offAH[4], offAL[4], offBH[2], offBL[2];
    {
        int rA = wm * 64 + (lane & 15);
        int sA = lane >> 4;
        #pragma unroll
        for (int mt = 0; mt < 4; mt++) {
            uint32_t base = (uint32_t)(rA + mt * 16) * 64u;
            offAH[mt] = sw64(base + (uint32_t)sA * 16u);
            offAL[mt] = sw64(base + (uint32_t)(2 + sA) * 16u);
        }
        int rB = wn * 32 + ((lane >> 4) << 3) + (lane & 7);
        int sB = (lane >> 3) & 1;
        #pragma unroll
        for (int np = 0; np < 2; np++) {
            uint32_t base = (uint32_t)(rB + np * 16) * 64u;
            offBH[np] = 8192u + sw64(base + (uint32_t)sB * 16u);
            offBL[np] = 8192u + sw64(base + (uint32_t)(2 + sB) * 16u);
        }
    }

    float acc[4][4][4];
    #pragma unroll
    for (int a = 0; a < 4; a++)
        #pragma unroll
        for (int b = 0; b < 4; b++)
            #pragma unroll
            for (int c = 0; c < 4; c++) acc[a][b][c] = 0.f;

    // ---- prologue: fill 3 stages ----
    #pragma unroll
    for (int p = 0; p < 3; p++) {
        uint32_t db = sb + (uint32_t)p * STAGE_BYTES;
        #pragma unroll
        for (int u = 0; u < 4; u++) cpasync16(db + dsto[u], srcp[u] + (size_t)p * 32);
        CP_COMMIT();
    }

    // ---- main loop over 64 k-stages ----
    for (int s = 0; s < NSTAGES_K; s++) {
        CP_WAIT2();
        __syncthreads();
        {   // prefetch stage s+3 into buffer (s+3)&3 (safe: computed at iter s-1)
            int sn = s + 3;
            if (sn < NSTAGES_K) {
                uint32_t db = sb + (uint32_t)(sn & 3) * STAGE_BYTES;
                #pragma unroll
                for (int u = 0; u < 4; u++) cpasync16(db + dsto[u], srcp[u] + (size_t)sn * 32);
            }
            CP_COMMIT();   // may be empty; keeps wait_group accounting uniform
        }
        const uint32_t base = sb + (uint32_t)(s & 3) * STAGE_BYTES;

        uint32_t BH[2][4], BL[2][4];
        #pragma unroll
        for (int np = 0; np < 2; np++) { LDM4(BH[np], base + offBH[np]); LDM4(BL[np], base + offBL[np]); }

        uint32_t AH[4][4];
        #pragma unroll
        for (int mt = 0; mt < 4; mt++) LDM4(AH[mt], base + offAH[mt]);
        #pragma unroll
        for (int mt = 0; mt < 4; mt++) {
            #pragma unroll
            for (int nt = 0; nt < 4; nt++) {
                MMA16816(acc[mt][nt], AH[mt], BH[nt >> 1][(nt & 1) * 2], BH[nt >> 1][(nt & 1) * 2 + 1]);
            }
            #pragma unroll
            for (int nt = 0; nt < 4; nt++) {
                MMA16816(acc[mt][nt], AH[mt], BL[nt >> 1][(nt & 1) * 2], BL[nt >> 1][(nt & 1) * 2 + 1]);
            }
        }
        uint32_t AL[4][4];
        #pragma unroll
        for (int mt = 0; mt < 4; mt++) LDM4(AL[mt], base + offAL[mt]);
        #pragma unroll
        for (int mt = 0; mt < 4; mt++)
            #pragma unroll
            for (int nt = 0; nt < 4; nt++) {
                MMA16816(acc[mt][nt], AL[mt], BH[nt >> 1][(nt & 1) * 2], BH[nt >> 1][(nt & 1) * 2 + 1]);
            }
    }
    CP_WAIT0();
    __syncthreads();   // stages dead; smem reused below

    // ---- epilogue: dist + top2/min ----
    const int tg = lane & 3, g = lane >> 2;
    float sqj[8]; int labj[8];
    #pragma unroll
    for (int ln = 0; ln < 8; ln++) {
        int cc = c0 + wn * 32 + (ln >> 1) * 8 + tg * 2 + (ln & 1);
        sqj[ln] = g_sq[cc];
        labj[ln] = getlab(lab, cc, lab64);
    }
    float b1v[8], b2v[8], mnv[8]; int b1i[8], b2i[8];
    #pragma unroll
    for (int lm = 0; lm < 8; lm++) {
        int m = r0 + wm * 64 + (lm >> 1) * 16 + g + (lm & 1) * 8;
        float sqi = g_sq[m];
        int labi = getlab(lab, m, lab64);
        float v1 = -INFINITY, v2 = -INFINITY, mn = INFINITY;
        int i1 = 0x7fffffff, i2 = 0x7fffffff;
        #pragma unroll
        for (int ln = 0; ln < 8; ln++) {
            int col = c0 + wn * 32 + (ln >> 1) * 8 + tg * 2 + (ln & 1);
            float dot = acc[lm >> 1][ln >> 1][(lm & 1) * 2 + (ln & 1)];
            float d2 = sqi + sqj[ln] - 2.0f * dot;
            float dist = sqrtf(fmaxf(d2, 1e-12f));
            bool same = (labi == labj[ln]);
            float pv = same ? dist : dist - BIGF;
            float nv = same ? dist + BIGF : dist;
            mn = fminf(mn, nv);
            if (keybetter(pv, col, v1, i1)) { v2 = v1; i2 = i1; v1 = pv; i1 = col; }
            else if (keybetter(pv, col, v2, i2)) { v2 = pv; i2 = col; }
        }
        b1v[lm] = v1; b1i[lm] = i1; b2v[lm] = v2; b2i[lm] = i2; mnv[lm] = mn;
    }
    // merge across the 4 tg lanes of each quad
    #pragma unroll
    for (int lm = 0; lm < 8; lm++) {
        #pragma unroll
        for (int off = 1; off <= 2; off <<= 1) {
            float o1v = __shfl_xor_sync(0xffffffffu, b1v[lm], off);
            int   o1i = __shfl_xor_sync(0xffffffffu, b1i[lm], off);
            float o2v = __shfl_xor_sync(0xffffffffu, b2v[lm], off);
            int   o2i = __shfl_xor_sync(0xffffffffu, b2i[lm], off);
            float omn = __shfl_xor_sync(0xffffffffu, mnv[lm], off);
            mnv[lm] = fminf(mnv[lm], omn);
            if (keybetter(o1v, o1i, b1v[lm], b1i[lm])) {
                if (keybetter(b1v[lm], b1i[lm], o2v, o2i)) { b2v[lm] = b1v[lm]; b2i[lm] = b1i[lm]; }
                else                                       { b2v[lm] = o2v;     b2i[lm] = o2i;     }
                b1v[lm] = o1v; b1i[lm] = o1i;
            } else if (keybetter(o1v, o1i, b2v[lm], b2i[lm])) { b2v[lm] = o1v; b2i[lm] = o1i; }
        }
    }
    // smem overlay: [128 rows][4 wn]
    float* sv1 = (float*)smem;
    float* sv2 = (float*)(smem + 2048);
    float* smn = (float*)(smem + 4096);
    int*   si1 = (int*)(smem + 6144);
    int*   si2 = (int*)(smem + 8192);
    if (tg == 0) {
        #pragma unroll
        for (int lm = 0; lm < 8; lm++) {
            int rl = wm * 64 + (lm >> 1) * 16 + g + (lm & 1) * 8;
            sv1[rl * 4 + wn] = b1v[lm]; si1[rl * 4 + wn] = b1i[lm];
            sv2[rl * 4 + wn] = b2v[lm]; si2[rl * 4 + wn] = b2i[lm];
            smn[rl * 4 + wn] = mnv[lm];
        }
    }
    __syncthreads();
    if (tid < 128) {
        float v1 = -INFINITY, v2 = -INFINITY, mn = INFINITY;
        int i1 = 0x7fffffff, i2 = 0x7fffffff;
        #pragma unroll
        for (int w = 0; w < 4; w++) {
            float o1v = sv1[tid * 4 + w]; int o1i = si1[tid * 4 + w];
            float o2v = sv2[tid * 4 + w]; int o2i = si2[tid * 4 + w];
            mn = fminf(mn, smn[tid * 4 + w]);
            if (keybetter(o1v, o1i, v1, i1)) {
                if (keybetter(v1, i1, o2v, o2i)) { v2 = v1; i2 = i1; }
                else                             { v2 = o2v; i2 = o2i; }
                v1 = o1v; i1 = o1i;
            } else if (keybetter(o1v, o1i, v2, i2)) { v2 = o1v; i2 = o1i; }
        }
        int r = r0 + tid, ct = blockIdx.x;
        g_p1v[ct][r] = v1; g_p1i[ct][r] = i1;
        g_p2v[ct][r] = v2; g_p2i[ct][r] = i2;
        g_pmn[ct][r] = mn;
    }
}

// ---------------- kernel 3: merge col-chunk partials per row ----------------
__global__ void k_merge() {
    int r = blockIdx.x * blockDim.x + threadIdx.x;
    if (r >= NROW) return;
    float b1v = -INFINITY, b2v = -INFINITY, mn = INFINITY;
    int b1i = 0x7fffffff, b2i = 0x7fffffff;
    for (int c = 0; c < NCT; c++) {
        float o1v = g_p1v[c][r]; int o1i = g_p1i[c][r];
        float o2v = g_p2v[c][r]; int o2i = g_p2i[c][r];
        mn = fminf(mn, g_pmn[c][r]);
        if (keybetter(o1v, o1i, b1v, b1i)) {
            if (keybetter(b1v, b1i, o2v, o2i)) { b2v = b1v; b2i = b1i; }
            else                               { b2v = o2v; b2i = o2i; }
            b1v = o1v; b1i = o1i;
        } else if (keybetter(o1v, o1i, b2v, b2i)) { b2v = o1v; b2i = o1i; }
    }
    g_ap1[r] = b1v; g_ap2[r] = b2v;
    g_j1[r] = b1i;  g_j2[r] = b2i;
    g_an[r] = mn;
}

// ---------------- kernel 4: cos at the two selected positives ----------------
__global__ void k_alpha(const float* __restrict__ clot) {
    int w = threadIdx.x >> 5, lane = threadIdx.x & 31;
    int r = blockIdx.x * 8 + w;
    int j1 = g_j1[r], j2 = g_j2[r];
    const float* cr = clot + (size_t)r * DIM2;
    const float* ca = clot + (size_t)j1 * DIM2;
    const float* cb = clot + (size_t)j2 * DIM2;
    float d1 = 0.f, d2 = 0.f;
    for (int k = lane; k < DIM2; k += 32) {
        float c = cr[k];
        d1 = fmaf(c, ca[k], d1);
        d2 = fmaf(c, cb[k], d2);
    }
    for (int o = 16; o > 0; o >>= 1) {
        d1 += __shfl_xor_sync(0xffffffffu, d1, o);
        d2 += __shfl_xor_sync(0xffffffffu, d2, o);
    }
    if (lane == 0) {
        g_a1[r] = d1 / (g_nrm[r] * g_nrm[j1]);
        g_a2[r] = d2 / (g_nrm[r] * g_nrm[j2]);
    }
}

// ---------------- kernel 5: final loss reduction ----------------
__global__ void k_final(float* __restrict__ out) {
    int t = threadIdx.x;
    double s11 = 0.0, s13 = 0.0, sp = 0.0;
    for (int r = t; r < NROW; r += 1024) {
        float ap1 = g_ap1[r], ap2 = g_ap2[r], an = g_an[r];
        float a1 = g_a1[r], a2 = g_a2[r];
        float y  = (a1 < a2) ? -1.f : 1.f;
        float ym = (a1 == a2) ? 0.f : 1.f;
        float x1 = ap2 * ym;
        float x2 = ap1 * ym + MARGINF * (a1 - a2 - y);
        float t11 = fmaxf(0.f, -y * (x1 - x2) + MARGINF);
        float ap1m = ap1 + MARGINF * (a1 - 1.f);
        float t13 = fmaxf(0.f, -(an - ap1m) + MARGINF);
        s11 += (double)t11; s13 += (double)t13;
        sp += (an > ap1m) ? 1.0 : 0.0;
    }
    __shared__ double r1[1024], r2[1024], r3[1024];
    r1[t] = s11; r2[t] = s13; r3[t] = sp;
    __syncthreads();
    for (int o = 512; o > 0; o >>= 1) {
        if (t < o) { r1[t] += r1[t + o]; r2[t] += r2[t + o]; r3[t] += r3[t + o]; }
        __syncthreads();
    }
    if (t == 0) {
        out[0] = (float)(0.1 * (r1[0] / NROW) + (r2[0] / NROW));
        out[1] = (float)(r3[0] / NROW);
    }
}

// ---------------- launch ----------------
extern "C" void kernel_launch(void* const* d_in, const int* in_sizes, int n_in,
                              void* d_out, int out_size) {
    const float* emb  = (const float*)d_in[0];
    const void*  lab  = d_in[1];
    const float* clot = (const float*)d_in[2];
    float* out = (float*)d_out;

    cudaFuncSetAttribute(k_dist_mma, cudaFuncAttributeMaxDynamicSharedMemorySize, SMEM_TOTAL);

    k_detect<<<1, 1>>>(lab);
    k_norms<<<NROW, 256>>>(emb, clot);
    k_split<<<NROW, 256>>>(emb);
    dim3 grid(NROW / BN, NROW / BM);
    k_dist_mma<<<grid, 256, SMEM_TOTAL>>>(lab);
    k_merge<<<NROW / 256, 256>>>();
    k_alpha<<<NROW / 8, 256>>>(clot);
    k_final<<<1, 1024>>>(out);
}

// round 4
// speedup vs baseline: 5.5118x; 1.5409x over previous
#include <cuda_runtime.h>
#include <cuda_bf16.h>
#include <math.h>
#include <stdint.h>

#define NROW 8192
#define DIM 1024
#define DIM2 512
#define BM 128
#define BN 128
#define NCT (NROW / BN)            // 64 partial slots
#define NTILE 2080                 // 64*65/2 upper-triangle tiles
#define BIGF 9999999.0f
#define MARGINF 0.3f

#define STAGE_BYTES 16384
#define NSTG 4
#define SMEM_TOTAL (NSTG * STAGE_BYTES)   // 64 KB
#define NSTAGES_K 64

// ---------------- device scratch ----------------
__device__ int   g_lab64;
__device__ float g_sq[NROW];
__device__ float g_nrm[NROW];
__device__ __nv_bfloat16 g_hi[(size_t)NROW * DIM];
__device__ __nv_bfloat16 g_lo[(size_t)NROW * DIM];
__device__ float g_p1v[NCT][NROW];
__device__ float g_p2v[NCT][NROW];
__device__ int   g_p1i[NCT][NROW];
__device__ int   g_p2i[NCT][NROW];
__device__ float g_pmn[NCT][NROW];
__device__ float g_ap1[NROW], g_ap2[NROW], g_an[NROW];
__device__ int   g_j1[NROW], g_j2[NROW];
__device__ float g_a1[NROW], g_a2[NROW];

// ---------------- helpers ----------------
__device__ __forceinline__ uint32_t smem_u32(const void* p) {
    uint32_t a;
    asm("{ .reg .u64 t; cvta.to.shared.u64 t, %1; cvt.u32.u64 %0, t; }" : "=r"(a) : "l"(p));
    return a;
}
__device__ __forceinline__ void cpasync16(uint32_t dst, const void* src) {
    asm volatile("cp.async.cg.shared.global [%0], [%1], 16;" :: "r"(dst), "l"(src));
}
#define CP_COMMIT() asm volatile("cp.async.commit_group;" ::: "memory")
#define CP_WAIT2()  asm volatile("cp.async.wait_group 2;" ::: "memory")
#define CP_WAIT0()  asm volatile("cp.async.wait_group 0;" ::: "memory")

#define LDM4(r, addr) \
    asm volatile("ldmatrix.sync.aligned.m8n8.x4.shared.b16 {%0,%1,%2,%3}, [%4];" \
        : "=r"((r)[0]), "=r"((r)[1]), "=r"((r)[2]), "=r"((r)[3]) : "r"(addr))

#define MMA16816(c, a, b0_, b1_) \
    asm volatile("mma.sync.aligned.m16n8k16.row.col.f32.bf16.bf16.f32 " \
        "{%0,%1,%2,%3}, {%4,%5,%6,%7}, {%8,%9}, {%0,%1,%2,%3};" \
        : "+f"((c)[0]), "+f"((c)[1]), "+f"((c)[2]), "+f"((c)[3]) \
        : "r"((a)[0]), "r"((a)[1]), "r"((a)[2]), "r"((a)[3]), "r"(b0_), "r"(b1_))

__device__ __forceinline__ int getlab(const void* lab, int i, int is64) {
    if (is64) return (int)((const long long*)lab)[i];
    return ((const int*)lab)[i];
}
__device__ __forceinline__ bool keybetter(float av, int ai, float bv, int bi) {
    return (av > bv) || (av == bv && ai < bi);
}
__device__ __forceinline__ uint32_t sw64(uint32_t off) { return off ^ ((off >> 3) & 0x30u); }

__device__ __forceinline__ void merge2(float& v1, int& i1, float& v2, int& i2,
                                       float o1v, int o1i, float o2v, int o2i) {
    if (keybetter(o1v, o1i, v1, i1)) {
        if (keybetter(v1, i1, o2v, o2i)) { v2 = v1; i2 = i1; }
        else                             { v2 = o2v; i2 = o2i; }
        v1 = o1v; i1 = o1i;
    } else if (keybetter(o1v, o1i, v2, i2)) { v2 = o1v; i2 = o1i; }
}

// ---------------- kernel 0: label width detect ----------------
__global__ void k_detect(const void* lab) {
    const unsigned* p = (const unsigned*)lab;
    int is64 = 1;
    for (int i = 0; i < 64; i++) if (p[2 * i + 1] != 0u) { is64 = 0; break; }
    g_lab64 = is64;
}

// ---------------- kernel 1: row norms ----------------
__global__ void k_norms(const float* __restrict__ emb, const float* __restrict__ clot) {
    int r = blockIdx.x, t = threadIdx.x;
    float4 v = ((const float4*)(emb + (size_t)r * DIM))[t];
    float s = v.x * v.x + v.y * v.y + v.z * v.z + v.w * v.w;
    float c = 0.f;
    if (t < DIM2 / 4) {
        float4 w = ((const float4*)(clot + (size_t)r * DIM2))[t];
        c = w.x * w.x + w.y * w.y + w.z * w.z + w.w * w.w;
    }
    __shared__ float se[256], sc[256];
    se[t] = s; sc[t] = c;
    __syncthreads();
    for (int o = 128; o > 0; o >>= 1) { if (t < o) { se[t] += se[t + o]; sc[t] += sc[t + o]; } __syncthreads(); }
    if (t == 0) { g_sq[r] = se[0]; g_nrm[r] = sqrtf(sc[0]); }
}

// ---------------- kernel 1b: split fp32 -> bf16 hi/lo ----------------
__global__ void k_split(const float* __restrict__ emb) {
    int r = blockIdx.x, t = threadIdx.x;
    float4 v = ((const float4*)(emb + (size_t)r * DIM))[t];
    float vv[4] = {v.x, v.y, v.z, v.w};
    __nv_bfloat16 h[4], l[4];
    #pragma unroll
    for (int i = 0; i < 4; i++) {
        h[i] = __float2bfloat16(vv[i]);
        l[i] = __float2bfloat16(vv[i] - __bfloat162float(h[i]));
    }
    size_t o = (size_t)r * DIM + t * 4;
    *(__nv_bfloat162*)(g_hi + o)     = __nv_bfloat162(h[0], h[1]);
    *(__nv_bfloat162*)(g_hi + o + 2) = __nv_bfloat162(h[2], h[3]);
    *(__nv_bfloat162*)(g_lo + o)     = __nv_bfloat162(l[0], l[1]);
    *(__nv_bfloat162*)(g_lo + o + 2) = __nv_bfloat162(l[2], l[3]);
}

// ---------------- kernel 2: HMMA split-bf16 GEMM, upper-triangle tiles ----------------
__global__ __launch_bounds__(256, 2) void k_dist_mma(const void* __restrict__ lab) {
    extern __shared__ char smem[];
    const uint32_t sb = smem_u32(smem);
    const int tid = threadIdx.x;
    const int lane = tid & 31, wid = tid >> 5;
    const int wm = wid >> 2, wn = wid & 3;
    const int lab64 = g_lab64;

    // decode linear tile id -> upper-triangle (rb, cb)
    int u = blockIdx.x, rb = 0;
    while (u >= 64 - rb) { u -= 64 - rb; rb++; }
    const int cb = rb + u;
    const int r0 = rb * BM, c0 = cb * BN;

    // ---- per-thread cp.async descriptors (4 x 16B per stage) ----
    const char* srcp[4];
    uint32_t dsto[4];
    #pragma unroll
    for (int v = 0; v < 4; v++) {
        int i = tid + v * 256;
        int tile = i >> 9;               // 0 = A, 1 = B
        int row = (i >> 2) & 127;
        int seg = i & 3;
        const __nv_bfloat16* sbase = (seg < 2) ? g_hi : g_lo;
        int grow = (tile ? c0 : r0) + row;
        srcp[v] = (const char*)(sbase + (size_t)grow * DIM + (seg & 1) * 8);
        dsto[v] = (uint32_t)tile * 8192u + sw64((uint32_t)row * 64u + (uint32_t)seg * 16u);
    }

    // ---- ldmatrix address offsets ----
    uint32_t offAH[4], offAL[4], offBH[2], offBL[2];
    {
        int rA = wm * 64 + (lane & 15);
        int sA = lane >> 4;
        #pragma unroll
        for (int mt = 0; mt < 4; mt++) {
            uint32_t base = (uint32_t)(rA + mt * 16) * 64u;
            offAH[mt] = sw64(base + (uint32_t)sA * 16u);
            offAL[mt] = sw64(base + (uint32_t)(2 + sA) * 16u);
        }
        int rB = wn * 32 + ((lane >> 4) << 3) + (lane & 7);
        int sB = (lane >> 3) & 1;
        #pragma unroll
        for (int np = 0; np < 2; np++) {
            uint32_t base = (uint32_t)(rB + np * 16) * 64u;
            offBH[np] = 8192u + sw64(base + (uint32_t)sB * 16u);
            offBL[np] = 8192u + sw64(base + (uint32_t)(2 + sB) * 16u);
        }
    }

    float acc[4][4][4];
    #pragma unroll
    for (int a = 0; a < 4; a++)
        #pragma unroll
        for (int b = 0; b < 4; b++)
            #pragma unroll
            for (int c = 0; c < 4; c++) acc[a][b][c] = 0.f;

    // ---- prologue ----
    #pragma unroll
    for (int p = 0; p < 3; p++) {
        uint32_t db = sb + (uint32_t)p * STAGE_BYTES;
        #pragma unroll
        for (int v = 0; v < 4; v++) cpasync16(db + dsto[v], srcp[v] + (size_t)p * 32);
        CP_COMMIT();
    }

    // ---- main loop ----
    for (int s = 0; s < NSTAGES_K; s++) {
        CP_WAIT2();
        __syncthreads();
        {
            int sn = s + 3;
            if (sn < NSTAGES_K) {
                uint32_t db = sb + (uint32_t)(sn & 3) * STAGE_BYTES;
                #pragma unroll
                for (int v = 0; v < 4; v++) cpasync16(db + dsto[v], srcp[v] + (size_t)sn * 32);
            }
            CP_COMMIT();
        }
        const uint32_t base = sb + (uint32_t)(s & 3) * STAGE_BYTES;

        uint32_t BH[2][4], BL[2][4];
        #pragma unroll
        for (int np = 0; np < 2; np++) { LDM4(BH[np], base + offBH[np]); LDM4(BL[np], base + offBL[np]); }

        uint32_t AH[4][4];
        #pragma unroll
        for (int mt = 0; mt < 4; mt++) LDM4(AH[mt], base + offAH[mt]);
        #pragma unroll
        for (int mt = 0; mt < 4; mt++) {
            #pragma unroll
            for (int nt = 0; nt < 4; nt++)
                MMA16816(acc[mt][nt], AH[mt], BH[nt >> 1][(nt & 1) * 2], BH[nt >> 1][(nt & 1) * 2 + 1]);
            #pragma unroll
            for (int nt = 0; nt < 4; nt++)
                MMA16816(acc[mt][nt], AH[mt], BL[nt >> 1][(nt & 1) * 2], BL[nt >> 1][(nt & 1) * 2 + 1]);
        }
        uint32_t AL[4][4];
        #pragma unroll
        for (int mt = 0; mt < 4; mt++) LDM4(AL[mt], base + offAL[mt]);
        #pragma unroll
        for (int mt = 0; mt < 4; mt++)
            #pragma unroll
            for (int nt = 0; nt < 4; nt++)
                MMA16816(acc[mt][nt], AL[mt], BH[nt >> 1][(nt & 1) * 2], BH[nt >> 1][(nt & 1) * 2 + 1]);
    }
    CP_WAIT0();
    __syncthreads();   // stages dead; smem reused below

    const int tg = lane & 3, g = lane >> 2;
    float sqj[8]; int labj[8];
    #pragma unroll
    for (int ln = 0; ln < 8; ln++) {
        int cc = c0 + wn * 32 + (ln >> 1) * 8 + tg * 2 + (ln & 1);
        sqj[ln] = g_sq[cc];
        labj[ln] = getlab(lab, cc, lab64);
    }
    float sqi[8]; int labi[8];
    #pragma unroll
    for (int lm = 0; lm < 8; lm++) {
        int m = r0 + wm * 64 + (lm >> 1) * 16 + g + (lm & 1) * 8;
        sqi[lm] = g_sq[m];
        labi[lm] = getlab(lab, m, lab64);
    }

    // smem overlays
    float* sv1 = (float*)smem;              // [128][4]
    float* sv2 = (float*)(smem + 2048);
    float* smn = (float*)(smem + 4096);
    int*   si1 = (int*)(smem + 6144);
    int*   si2 = (int*)(smem + 8192);
    float* cv1 = (float*)(smem + 16384);    // [128][2]
    float* cv2 = (float*)(smem + 17408);
    float* cmn = (float*)(smem + 18432);
    int*   ci1 = (int*)(smem + 19456);
    int*   ci2 = (int*)(smem + 20480);

    // ======== row stats ========
    {
        float b1v[8], b2v[8], mnv[8]; int b1i[8], b2i[8];
        #pragma unroll
        for (int lm = 0; lm < 8; lm++) {
            float v1 = -INFINITY, v2 = -INFINITY, mn = INFINITY;
            int i1 = 0x7fffffff, i2 = 0x7fffffff;
            #pragma unroll
            for (int ln = 0; ln < 8; ln++) {
                int col = c0 + wn * 32 + (ln >> 1) * 8 + tg * 2 + (ln & 1);
                float dot = acc[lm >> 1][ln >> 1][(lm & 1) * 2 + (ln & 1)];
                float d2 = sqi[lm] + sqj[ln] - 2.0f * dot;
                float dist = sqrtf(fmaxf(d2, 1e-12f));
                bool same = (labi[lm] == labj[ln]);
                float pv = same ? dist : dist - BIGF;
                float nv = same ? dist + BIGF : dist;
                mn = fminf(mn, nv);
                if (keybetter(pv, col, v1, i1)) { v2 = v1; i2 = i1; v1 = pv; i1 = col; }
                else if (keybetter(pv, col, v2, i2)) { v2 = pv; i2 = col; }
            }
            b1v[lm] = v1; b1i[lm] = i1; b2v[lm] = v2; b2i[lm] = i2; mnv[lm] = mn;
        }
        #pragma unroll
        for (int lm = 0; lm < 8; lm++) {
            #pragma unroll
            for (int off = 1; off <= 2; off <<= 1) {
                float o1v = __shfl_xor_sync(0xffffffffu, b1v[lm], off);
                int   o1i = __shfl_xor_sync(0xffffffffu, b1i[lm], off);
                float o2v = __shfl_xor_sync(0xffffffffu, b2v[lm], off);
                int   o2i = __shfl_xor_sync(0xffffffffu, b2i[lm], off);
                float omn = __shfl_xor_sync(0xffffffffu, mnv[lm], off);
                mnv[lm] = fminf(mnv[lm], omn);
                merge2(b1v[lm], b1i[lm], b2v[lm], b2i[lm], o1v, o1i, o2v, o2i);
            }
        }
        if (tg == 0) {
            #pragma unroll
            for (int lm = 0; lm < 8; lm++) {
                int rl = wm * 64 + (lm >> 1) * 16 + g + (lm & 1) * 8;
                sv1[rl * 4 + wn] = b1v[lm]; si1[rl * 4 + wn] = b1i[lm];
                sv2[rl * 4 + wn] = b2v[lm]; si2[rl * 4 + wn] = b2i[lm];
                smn[rl * 4 + wn] = mnv[lm];
            }
        }
    }

    // ======== col stats (transposed harvest; skip on diagonal) ========
    if (rb != cb) {
        float b1v[8], b2v[8], mnv[8]; int b1i[8], b2i[8];
        #pragma unroll
        for (int ln = 0; ln < 8; ln++) {
            float v1 = -INFINITY, v2 = -INFINITY, mn = INFINITY;
            int i1 = 0x7fffffff, i2 = 0x7fffffff;
            #pragma unroll
            for (int lm = 0; lm < 8; lm++) {
                int rowidx = r0 + wm * 64 + (lm >> 1) * 16 + g + (lm & 1) * 8;
                float dot = acc[lm >> 1][ln >> 1][(lm & 1) * 2 + (ln & 1)];
                float d2 = sqi[lm] + sqj[ln] - 2.0f * dot;
                float dist = sqrtf(fmaxf(d2, 1e-12f));
                bool same = (labi[lm] == labj[ln]);
                float pv = same ? dist : dist - BIGF;
                float nv = same ? dist + BIGF : dist;
                mn = fminf(mn, nv);
                if (keybetter(pv, rowidx, v1, i1)) { v2 = v1; i2 = i1; v1 = pv; i1 = rowidx; }
                else if (keybetter(pv, rowidx, v2, i2)) { v2 = pv; i2 = rowidx; }
            }
            b1v[ln] = v1; b1i[ln] = i1; b2v[ln] = v2; b2i[ln] = i2; mnv[ln] = mn;
        }
        #pragma unroll
        for (int ln = 0; ln < 8; ln++) {
            #pragma unroll
            for (int off = 4; off <= 16; off <<= 1) {
                float o1v = __shfl_xor_sync(0xffffffffu, b1v[ln], off);
                int   o1i = __shfl_xor_sync(0xffffffffu, b1i[ln], off);
                float o2v = __shfl_xor_sync(0xffffffffu, b2v[ln], off);
                int   o2i = __shfl_xor_sync(0xffffffffu, b2i[ln], off);
                float omn = __shfl_xor_sync(0xffffffffu, mnv[ln], off);
                mnv[ln] = fminf(mnv[ln], omn);
                merge2(b1v[ln], b1i[ln], b2v[ln], b2i[ln], o1v, o1i, o2v, o2i);
            }
        }
        if (g == 0) {
            #pragma unroll
            for (int ln = 0; ln < 8; ln++) {
                int cl = wn * 32 + (ln >> 1) * 8 + tg * 2 + (ln & 1);
                cv1[cl * 2 + wm] = b1v[ln]; ci1[cl * 2 + wm] = b1i[ln];
                cv2[cl * 2 + wm] = b2v[ln]; ci2[cl * 2 + wm] = b2i[ln];
                cmn[cl * 2 + wm] = mnv[ln];
            }
        }
    }
    __syncthreads();

    // final merges + global writes
    if (tid < 128) {
        {
            float v1 = -INFINITY, v2 = -INFINITY, mn = INFINITY;
            int i1 = 0x7fffffff, i2 = 0x7fffffff;
            #pragma unroll
            for (int w = 0; w < 4; w++) {
                mn = fminf(mn, smn[tid * 4 + w]);
                merge2(v1, i1, v2, i2, sv1[tid * 4 + w], si1[tid * 4 + w], sv2[tid * 4 + w], si2[tid * 4 + w]);
            }
            int r = r0 + tid;
            g_p1v[cb][r] = v1; g_p1i[cb][r] = i1;
            g_p2v[cb][r] = v2; g_p2i[cb][r] = i2;
            g_pmn[cb][r] = mn;
        }
        if (rb != cb) {
            float v1 = -INFINITY, v2 = -INFINITY, mn = INFINITY;
            int i1 = 0x7fffffff, i2 = 0x7fffffff;
            #pragma unroll
            for (int w = 0; w < 2; w++) {
                mn = fminf(mn, cmn[tid * 2 + w]);
                merge2(v1, i1, v2, i2, cv1[tid * 2 + w], ci1[tid * 2 + w], cv2[tid * 2 + w], ci2[tid * 2 + w]);
            }
            int r = c0 + tid;
            g_p1v[rb][r] = v1; g_p1i[rb][r] = i1;
            g_p2v[rb][r] = v2; g_p2i[rb][r] = i2;
            g_pmn[rb][r] = mn;
        }
    }
}

// ---------------- kernel 3: merge partials per row ----------------
__global__ void k_merge() {
    int r = blockIdx.x * blockDim.x + threadIdx.x;
    if (r >= NROW) return;
    float b1v = -INFINITY, b2v = -INFINITY, mn = INFINITY;
    int b1i = 0x7fffffff, b2i = 0x7fffffff;
    for (int c = 0; c < NCT; c++) {
        mn = fminf(mn, g_pmn[c][r]);
        merge2(b1v, b1i, b2v, b2i, g_p1v[c][r], g_p1i[c][r], g_p2v[c][r], g_p2i[c][r]);
    }
    g_ap1[r] = b1v; g_ap2[r] = b2v;
    g_j1[r] = b1i;  g_j2[r] = b2i;
    g_an[r] = mn;
}

// ---------------- kernel 4: cos at the two selected positives ----------------
__global__ void k_alpha(const float* __restrict__ clot) {
    int w = threadIdx.x >> 5, lane = threadIdx.x & 31;
    int r = blockIdx.x * 8 + w;
    int j1 = g_j1[r], j2 = g_j2[r];
    const float* cr = clot + (size_t)r * DIM2;
    const float* ca = clot + (size_t)j1 * DIM2;
    const float* cb = clot + (size_t)j2 * DIM2;
    float d1 = 0.f, d2 = 0.f;
    for (int k = lane; k < DIM2; k += 32) {
        float c = cr[k];
        d1 = fmaf(c, ca[k], d1);
        d2 = fmaf(c, cb[k], d2);
    }
    for (int o = 16; o > 0; o >>= 1) {
        d1 += __shfl_xor_sync(0xffffffffu, d1, o);
        d2 += __shfl_xor_sync(0xffffffffu, d2, o);
    }
    if (lane == 0) {
        g_a1[r] = d1 / (g_nrm[r] * g_nrm[j1]);
        g_a2[r] = d2 / (g_nrm[r] * g_nrm[j2]);
    }
}

// ---------------- kernel 5: final loss reduction ----------------
__global__ void k_final(float* __restrict__ out) {
    int t = threadIdx.x;
    double s11 = 0.0, s13 = 0.0, sp = 0.0;
    for (int r = t; r < NROW; r += 1024) {
        float ap1 = g_ap1[r], ap2 = g_ap2[r], an = g_an[r];
        float a1 = g_a1[r], a2 = g_a2[r];
        float y  = (a1 < a2) ? -1.f : 1.f;
        float ym = (a1 == a2) ? 0.f : 1.f;
        float x1 = ap2 * ym;
        float x2 = ap1 * ym + MARGINF * (a1 - a2 - y);
        float t11 = fmaxf(0.f, -y * (x1 - x2) + MARGINF);
        float ap1m = ap1 + MARGINF * (a1 - 1.f);
        float t13 = fmaxf(0.f, -(an - ap1m) + MARGINF);
        s11 += (double)t11; s13 += (double)t13;
        sp += (an > ap1m) ? 1.0 : 0.0;
    }
    __shared__ double r1[1024], r2[1024], r3[1024];
    r1[t] = s11; r2[t] = s13; r3[t] = sp;
    __syncthreads();
    for (int o = 512; o > 0; o >>= 1) {
        if (t < o) { r1[t] += r1[t + o]; r2[t] += r2[t + o]; r3[t] += r3[t + o]; }
        __syncthreads();
    }
    if (t == 0) {
        out[0] = (float)(0.1 * (r1[0] / NROW) + (r2[0] / NROW));
        out[1] = (float)(r3[0] / NROW);
    }
}

// ---------------- launch ----------------
extern "C" void kernel_launch(void* const* d_in, const int* in_sizes, int n_in,
                              void* d_out, int out_size) {
    const float* emb  = (const float*)d_in[0];
    const void*  lab  = d_in[1];
    const float* clot = (const float*)d_in[2];
    float* out = (float*)d_out;

    cudaFuncSetAttribute(k_dist_mma, cudaFuncAttributeMaxDynamicSharedMemorySize, SMEM_TOTAL);

    k_detect<<<1, 1>>>(lab);
    k_norms<<<NROW, 256>>>(emb, clot);
    k_split<<<NROW, 256>>>(emb);
    k_dist_mma<<<NTILE, 256, SMEM_TOTAL>>>(lab);
    k_merge<<<NROW / 256, 256>>>();
    k_alpha<<<NROW / 8, 256>>>(clot);
    k_final<<<1, 1024>>>(out);
}

// round 6
// speedup vs baseline: 7.4400x; 1.3498x over previous
#include <cuda_runtime.h>
#include <cuda_fp16.h>
#include <math.h>
#include <stdint.h>

#define NROW 8192
#define DIM 1024
#define DIM2 512
#define BM 128
#define BN 128
#define NCT (NROW / BN)            // 64 partial slots
#define NTILE 2080                 // 64*65/2 upper-triangle tiles
#define BIGF 9999999.0f
#define MARGINF 0.3f

#define STAGE_BYTES 24576          // A hi (128x64B) + B hi|lo (128x128B)
#define B_OFF 8192
#define NSTG 4
#define SMEM_TOTAL (NSTG * STAGE_BYTES)   // 96 KB
#define NSTAGES_K 32               // 1024 / 32

// ---------------- device scratch ----------------
__device__ int   g_lab64;
__device__ float g_sq[NROW];
__device__ float g_nrm[NROW];
__device__ __half g_hi[(size_t)NROW * DIM];
__device__ __half g_lo[(size_t)NROW * DIM];
__device__ float g_p1v[NCT][NROW];
__device__ float g_p2v[NCT][NROW];
__device__ int   g_p1i[NCT][NROW];
__device__ int   g_p2i[NCT][NROW];
__device__ float g_pmn[NCT][NROW];
__device__ float g_ap1[NROW], g_ap2[NROW], g_an[NROW];
__device__ int   g_j1[NROW], g_j2[NROW];
__device__ float g_a1[NROW], g_a2[NROW];

// ---------------- helpers ----------------
__device__ __forceinline__ uint32_t smem_u32(const void* p) {
    uint32_t a;
    asm("{ .reg .u64 t; cvta.to.shared.u64 t, %1; cvt.u32.u64 %0, t; }" : "=r"(a) : "l"(p));
    return a;
}
__device__ __forceinline__ void cpasync16(uint32_t dst, const void* src) {
    asm volatile("cp.async.cg.shared.global [%0], [%1], 16;" :: "r"(dst), "l"(src));
}
#define CP_COMMIT() asm volatile("cp.async.commit_group;" ::: "memory")
#define CP_WAIT2()  asm volatile("cp.async.wait_group 2;" ::: "memory")
#define CP_WAIT0()  asm volatile("cp.async.wait_group 0;" ::: "memory")

#define LDM4(r, addr) \
    asm volatile("ldmatrix.sync.aligned.m8n8.x4.shared.b16 {%0,%1,%2,%3}, [%4];" \
        : "=r"((r)[0]), "=r"((r)[1]), "=r"((r)[2]), "=r"((r)[3]) : "r"(addr))

#define MMA16816(c, a, b0_, b1_) \
    asm volatile("mma.sync.aligned.m16n8k16.row.col.f32.f16.f16.f32 " \
        "{%0,%1,%2,%3}, {%4,%5,%6,%7}, {%8,%9}, {%0,%1,%2,%3};" \
        : "+f"((c)[0]), "+f"((c)[1]), "+f"((c)[2]), "+f"((c)[3]) \
        : "r"((a)[0]), "r"((a)[1]), "r"((a)[2]), "r"((a)[3]), "r"(b0_), "r"(b1_))

__device__ __forceinline__ int getlab(const void* lab, int i, int is64) {
    if (is64) return (int)((const long long*)lab)[i];
    return ((const int*)lab)[i];
}
__device__ __forceinline__ bool keybetter(float av, int ai, float bv, int bi) {
    return (av > bv) || (av == bv && ai < bi);
}
__device__ __forceinline__ uint32_t sw64(uint32_t off)  { return off ^ ((off >> 3) & 0x30u); }
__device__ __forceinline__ uint32_t sw128(uint32_t off) { return off ^ ((off >> 3) & 0x70u); }

__device__ __forceinline__ void merge2(float& v1, int& i1, float& v2, int& i2,
                                       float o1v, int o1i, float o2v, int o2i) {
    if (keybetter(o1v, o1i, v1, i1)) {
        if (keybetter(v1, i1, o2v, o2i)) { v2 = v1; i2 = i1; }
        else                             { v2 = o2v; i2 = o2i; }
        v1 = o1v; i1 = o1i;
    } else if (keybetter(o1v, o1i, v2, i2)) { v2 = o1v; i2 = o1i; }
}

// ---------------- kernel 0: label width detect ----------------
__global__ void k_detect(const void* lab) {
    const unsigned* p = (const unsigned*)lab;
    int is64 = 1;
    for (int i = 0; i < 64; i++) if (p[2 * i + 1] != 0u) { is64 = 0; break; }
    g_lab64 = is64;
}

// ---------------- kernel 1: fused norms + fp16 hi/lo split ----------------
__global__ void k_prep(const float* __restrict__ emb, const float* __restrict__ clot) {
    int r = blockIdx.x, t = threadIdx.x;
    float4 v = ((const float4*)(emb + (size_t)r * DIM))[t];
    float vv[4] = {v.x, v.y, v.z, v.w};
    float s = v.x * v.x + v.y * v.y + v.z * v.z + v.w * v.w;
    __half h[4], l[4];
    #pragma unroll
    for (int i = 0; i < 4; i++) {
        h[i] = __float2half(vv[i]);
        l[i] = __float2half(vv[i] - __half2float(h[i]));
    }
    size_t o = (size_t)r * DIM + t * 4;
    *(__half2*)(g_hi + o)     = __half2(h[0], h[1]);
    *(__half2*)(g_hi + o + 2) = __half2(h[2], h[3]);
    *(__half2*)(g_lo + o)     = __half2(l[0], l[1]);
    *(__half2*)(g_lo + o + 2) = __half2(l[2], l[3]);
    float c = 0.f;
    if (t < DIM2 / 4) {
        float4 w = ((const float4*)(clot + (size_t)r * DIM2))[t];
        c = w.x * w.x + w.y * w.y + w.z * w.z + w.w * w.w;
    }
    __shared__ float se[256], sc[256];
    se[t] = s; sc[t] = c;
    __syncthreads();
    for (int o2 = 128; o2 > 0; o2 >>= 1) { if (t < o2) { se[t] += se[t + o2]; sc[t] += sc[t + o2]; } __syncthreads(); }
    if (t == 0) { g_sq[r] = se[0]; g_nrm[r] = sqrtf(sc[0]); }
}

// ---------------- kernel 2: fp16 2-pass HMMA GEMM, upper-triangle tiles ----------------
// stage: A @0: 128 rows x 64B (hi, k0..31); B @8192: 128 rows x 128B (hi k0..31 | lo k0..31)
__global__ __launch_bounds__(256, 2) void k_dist_mma(const void* __restrict__ lab) {
    extern __shared__ char smem[];
    const uint32_t sb = smem_u32(smem);
    const int tid = threadIdx.x;
    const int lane = tid & 31, wid = tid >> 5;
    const int wm = wid >> 2, wn = wid & 3;
    const int lab64 = g_lab64;

    // decode linear tile id -> upper-triangle (rb, cb)
    int u = blockIdx.x, rb = 0;
    while (u >= 64 - rb) { u -= 64 - rb; rb++; }
    const int cb = rb + u;
    const int r0 = rb * BM, c0 = cb * BN;

    // ---- per-thread cp.async descriptors (6 x 16B per stage) ----
    const char* srcp[6];
    uint32_t dsto[6];
    #pragma unroll
    for (int v = 0; v < 2; v++) {          // A hi: 512 ops
        int i = tid + v * 256;
        int row = i >> 2, seg = i & 3;
        srcp[v] = (const char*)(g_hi + (size_t)(r0 + row) * DIM + seg * 8);
        dsto[v] = sw64((uint32_t)row * 64u + (uint32_t)seg * 16u);
    }
    #pragma unroll
    for (int v = 2; v < 6; v++) {          // B hi|lo: 1024 ops
        int j = tid + (v - 2) * 256;
        int row = j >> 3, seg = j & 7;
        const __half* sbase = (seg < 4) ? g_hi : g_lo;
        srcp[v] = (const char*)(sbase + (size_t)(c0 + row) * DIM + (seg & 3) * 8);
        dsto[v] = B_OFF + sw128((uint32_t)row * 128u + (uint32_t)seg * 16u);
    }

    // ---- ldmatrix pre-offsets + row-dependent swizzle masks ----
    // swizzle mask depends only on row bits (>=7); intra-row additions (kd, +64)
    // never carry into them, so addr = (pre + delta) ^ mask is exact.
    uint32_t preA[4], mskA[4], preB[2], mskB[2];
    {
        int rA = wm * 64 + (lane & 15);
        int sA = lane >> 4;
        #pragma unroll
        for (int mt = 0; mt < 4; mt++) {
            uint32_t p = (uint32_t)(rA + mt * 16) * 64u + (uint32_t)sA * 16u;
            mskA[mt] = (p >> 3) & 0x30u;
            preA[mt] = p;
        }
        int rB = wn * 32 + ((lane >> 4) << 3) + (lane & 7);
        int sB = (lane >> 3) & 1;
        #pragma unroll
        for (int np = 0; np < 2; np++) {
            uint32_t p = (uint32_t)(rB + np * 16) * 128u + (uint32_t)sB * 16u;
            mskB[np] = (p >> 3) & 0x70u;
            preB[np] = p;
        }
    }

    float acc[4][4][4];
    #pragma unroll
    for (int a = 0; a < 4; a++)
        #pragma unroll
        for (int b = 0; b < 4; b++)
            #pragma unroll
            for (int c = 0; c < 4; c++) acc[a][b][c] = 0.f;

    // ---- prologue: fill 3 stages ----
    #pragma unroll
    for (int p = 0; p < 3; p++) {
        uint32_t db = sb + (uint32_t)p * STAGE_BYTES;
        #pragma unroll
        for (int v = 0; v < 6; v++) cpasync16(db + dsto[v], srcp[v] + (size_t)p * 64);
        CP_COMMIT();
    }

    // ---- main loop: 32 K-stages of 32 ----
    for (int s = 0; s < NSTAGES_K; s++) {
        CP_WAIT2();
        __syncthreads();
        {
            int sn = s + 3;
            if (sn < NSTAGES_K) {
                uint32_t db = sb + (uint32_t)(sn & 3) * STAGE_BYTES;
                #pragma unroll
                for (int v = 0; v < 6; v++) cpasync16(db + dsto[v], srcp[v] + (size_t)sn * 64);
            }
            CP_COMMIT();
        }
        const uint32_t base = sb + (uint32_t)(s & 3) * STAGE_BYTES;
        const uint32_t baseB = base + B_OFF;

        #pragma unroll
        for (int kc = 0; kc < 2; kc++) {
            const uint32_t kd = (uint32_t)kc * 32u;
            uint32_t BH[2][4], BL[2][4];
            #pragma unroll
            for (int np = 0; np < 2; np++) {
                LDM4(BH[np], baseB + ((preB[np] + kd) ^ mskB[np]));
                LDM4(BL[np], baseB + ((preB[np] + kd + 64u) ^ mskB[np]));
            }
            uint32_t AH[4][4];
            #pragma unroll
            for (int mt = 0; mt < 4; mt++) LDM4(AH[mt], base + ((preA[mt] + kd) ^ mskA[mt]));
            #pragma unroll
            for (int mt = 0; mt < 4; mt++) {
                #pragma unroll
                for (int nt = 0; nt < 4; nt++)
                    MMA16816(acc[mt][nt], AH[mt], BH[nt >> 1][(nt & 1) * 2], BH[nt >> 1][(nt & 1) * 2 + 1]);
                #pragma unroll
                for (int nt = 0; nt < 4; nt++)
                    MMA16816(acc[mt][nt], AH[mt], BL[nt >> 1][(nt & 1) * 2], BL[nt >> 1][(nt & 1) * 2 + 1]);
            }
        }
    }
    CP_WAIT0();
    __syncthreads();   // stages dead; smem reused below

    const int tg = lane & 3, g = lane >> 2;
    float sqj[8]; int labj[8];
    #pragma unroll
    for (int ln = 0; ln < 8; ln++) {
        int cc = c0 + wn * 32 + (ln >> 1) * 8 + tg * 2 + (ln & 1);
        sqj[ln] = g_sq[cc];
        labj[ln] = getlab(lab, cc, lab64);
    }
    float sqi[8]; int labi[8];
    #pragma unroll
    for (int lm = 0; lm < 8; lm++) {
        int m = r0 + wm * 64 + (lm >> 1) * 16 + g + (lm & 1) * 8;
        sqi[lm] = g_sq[m];
        labi[lm] = getlab(lab, m, lab64);
    }

    // smem overlays
    float* sv1 = (float*)smem;              // [128][4]
    float* sv2 = (float*)(smem + 2048);
    float* smn = (float*)(smem + 4096);
    int*   si1 = (int*)(smem + 6144);
    int*   si2 = (int*)(smem + 8192);
    float* cv1 = (float*)(smem + 16384);    // [128][2]
    float* cv2 = (float*)(smem + 17408);
    float* cmn = (float*)(smem + 18432);
    int*   ci1 = (int*)(smem + 19456);
    int*   ci2 = (int*)(smem + 20480);

    // ======== row stats ========
    {
        float b1v[8], b2v[8], mnv[8]; int b1i[8], b2i[8];
        #pragma unroll
        for (int lm = 0; lm < 8; lm++) {
            float v1 = -INFINITY, v2 = -INFINITY, mn = INFINITY;
            int i1 = 0x7fffffff, i2 = 0x7fffffff;
            #pragma unroll
            for (int ln = 0; ln < 8; ln++) {
                int col = c0 + wn * 32 + (ln >> 1) * 8 + tg * 2 + (ln & 1);
                float dot = acc[lm >> 1][ln >> 1][(lm & 1) * 2 + (ln & 1)];
                float d2 = sqi[lm] + sqj[ln] - 2.0f * dot;
                float dist = sqrtf(fmaxf(d2, 1e-12f));
                bool same = (labi[lm] == labj[ln]);
                float pv = same ? dist : dist - BIGF;
                float nv = same ? dist + BIGF : dist;
                mn = fminf(mn, nv);
                if (keybetter(pv, col, v1, i1)) { v2 = v1; i2 = i1; v1 = pv; i1 = col; }
                else if (keybetter(pv, col, v2, i2)) { v2 = pv; i2 = col; }
            }
            b1v[lm] = v1; b1i[lm] = i1; b2v[lm] = v2; b2i[lm] = i2; mnv[lm] = mn;
        }
        #pragma unroll
        for (int lm = 0; lm < 8; lm++) {
            #pragma unroll
            for (int off = 1; off <= 2; off <<= 1) {
                float o1v = __shfl_xor_sync(0xffffffffu, b1v[lm], off);
                int   o1i = __shfl_xor_sync(0xffffffffu, b1i[lm], off);
                float o2v = __shfl_xor_sync(0xffffffffu, b2v[lm], off);
                int   o2i = __shfl_xor_sync(0xffffffffu, b2i[lm], off);
                float omn = __shfl_xor_sync(0xffffffffu, mnv[lm], off);
                mnv[lm] = fminf(mnv[lm], omn);
                merge2(b1v[lm], b1i[lm], b2v[lm], b2i[lm], o1v, o1i, o2v, o2i);
            }
        }
        if (tg == 0) {
            #pragma unroll
            for (int lm = 0; lm < 8; lm++) {
                int rl = wm * 64 + (lm >> 1) * 16 + g + (lm & 1) * 8;
                sv1[rl * 4 + wn] = b1v[lm]; si1[rl * 4 + wn] = b1i[lm];
                sv2[rl * 4 + wn] = b2v[lm]; si2[rl * 4 + wn] = b2i[lm];
                smn[rl * 4 + wn] = mnv[lm];
            }
        }
    }

    // ======== col stats (transposed harvest; skip on diagonal) ========
    if (rb != cb) {
        float b1v[8], b2v[8], mnv[8]; int b1i[8], b2i[8];
        #pragma unroll
        for (int ln = 0; ln < 8; ln++) {
            float v1 = -INFINITY, v2 = -INFINITY, mn = INFINITY;
            int i1 = 0x7fffffff, i2 = 0x7fffffff;
            #pragma unroll
            for (int lm = 0; lm < 8; lm++) {
                int rowidx = r0 + wm * 64 + (lm >> 1) * 16 + g + (lm & 1) * 8;
                float dot = acc[lm >> 1][ln >> 1][(lm & 1) * 2 + (ln & 1)];
                float d2 = sqi[lm] + sqj[ln] - 2.0f * dot;
                float dist = sqrtf(fmaxf(d2, 1e-12f));
                bool same = (labi[lm] == labj[ln]);
                float pv = same ? dist : dist - BIGF;
                float nv = same ? dist + BIGF : dist;
                mn = fminf(mn, nv);
                if (keybetter(pv, rowidx, v1, i1)) { v2 = v1; i2 = i1; v1 = pv; i1 = rowidx; }
                else if (keybetter(pv, rowidx, v2, i2)) { v2 = pv; i2 = rowidx; }
            }
            b1v[ln] = v1; b1i[ln] = i1; b2v[ln] = v2; b2i[ln] = i2; mnv[ln] = mn;
        }
        #pragma unroll
        for (int ln = 0; ln < 8; ln++) {
            #pragma unroll
            for (int off = 4; off <= 16; off <<= 1) {
                float o1v = __shfl_xor_sync(0xffffffffu, b1v[ln], off);
                int   o1i = __shfl_xor_sync(0xffffffffu, b1i[ln], off);
                float o2v = __shfl_xor_sync(0xffffffffu, b2v[ln], off);
                int   o2i = __shfl_xor_sync(0xffffffffu, b2i[ln], off);
                float omn = __shfl_xor_sync(0xffffffffu, mnv[ln], off);
                mnv[ln] = fminf(mnv[ln], omn);
                merge2(b1v[ln], b1i[ln], b2v[ln], b2i[ln], o1v, o1i, o2v, o2i);
            }
        }
        if (g == 0) {
            #pragma unroll
            for (int ln = 0; ln < 8; ln++) {
                int cl = wn * 32 + (ln >> 1) * 8 + tg * 2 + (ln & 1);
                cv1[cl * 2 + wm] = b1v[ln]; ci1[cl * 2 + wm] = b1i[ln];
                cv2[cl * 2 + wm] = b2v[ln]; ci2[cl * 2 + wm] = b2i[ln];
                cmn[cl * 2 + wm] = mnv[ln];
            }
        }
    }
    __syncthreads();

    // final merges + global writes
    if (tid < 128) {
        {
            float v1 = -INFINITY, v2 = -INFINITY, mn = INFINITY;
            int i1 = 0x7fffffff, i2 = 0x7fffffff;
            #pragma unroll
            for (int w = 0; w < 4; w++) {
                mn = fminf(mn, smn[tid * 4 + w]);
                merge2(v1, i1, v2, i2, sv1[tid * 4 + w], si1[tid * 4 + w], sv2[tid * 4 + w], si2[tid * 4 + w]);
            }
            int r = r0 + tid;
            g_p1v[cb][r] = v1; g_p1i[cb][r] = i1;
            g_p2v[cb][r] = v2; g_p2i[cb][r] = i2;
            g_pmn[cb][r] = mn;
        }
        if (rb != cb) {
            float v1 = -INFINITY, v2 = -INFINITY, mn = INFINITY;
            int i1 = 0x7fffffff, i2 = 0x7fffffff;
            #pragma unroll
            for (int w = 0; w < 2; w++) {
                mn = fminf(mn, cmn[tid * 2 + w]);
                merge2(v1, i1, v2, i2, cv1[tid * 2 + w], ci1[tid * 2 + w], cv2[tid * 2 + w], ci2[tid * 2 + w]);
            }
            int r = c0 + tid;
            g_p1v[rb][r] = v1; g_p1i[rb][r] = i1;
            g_p2v[rb][r] = v2; g_p2i[rb][r] = i2;
            g_pmn[rb][r] = mn;
        }
    }
}

// ---------------- kernel 3: merge partials per row ----------------
__global__ void k_merge() {
    int r = blockIdx.x * blockDim.x + threadIdx.x;
    if (r >= NROW) return;
    float b1v = -INFINITY, b2v = -INFINITY, mn = INFINITY;
    int b1i = 0x7fffffff, b2i = 0x7fffffff;
    for (int c = 0; c < NCT; c++) {
        mn = fminf(mn, g_pmn[c][r]);
        merge2(b1v, b1i, b2v, b2i, g_p1v[c][r], g_p1i[c][r], g_p2v[c][r], g_p2i[c][r]);
    }
    g_ap1[r] = b1v; g_ap2[r] = b2v;
    g_j1[r] = b1i;  g_j2[r] = b2i;
    g_an[r] = mn;
}

// ---------------- kernel 4: cos at the two selected positives ----------------
__global__ void k_alpha(const float* __restrict__ clot) {
    int w = threadIdx.x >> 5, lane = threadIdx.x & 31;
    int r = blockIdx.x * 8 + w;
    int j1 = g_j1[r], j2 = g_j2[r];
    const float* cr = clot + (size_t)r * DIM2;
    const float* ca = clot + (size_t)j1 * DIM2;
    const float* cb = clot + (size_t)j2 * DIM2;
    float d1 = 0.f, d2 = 0.f;
    for (int k = lane; k < DIM2; k += 32) {
        float c = cr[k];
        d1 = fmaf(c, ca[k], d1);
        d2 = fmaf(c, cb[k], d2);
    }
    for (int o = 16; o > 0; o >>= 1) {
        d1 += __shfl_xor_sync(0xffffffffu, d1, o);
        d2 += __shfl_xor_sync(0xffffffffu, d2, o);
    }
    if (lane == 0) {
        g_a1[r] = d1 / (g_nrm[r] * g_nrm[j1]);
        g_a2[r] = d2 / (g_nrm[r] * g_nrm[j2]);
    }
}

// ---------------- kernel 5: final loss reduction ----------------
__global__ void k_final(float* __restrict__ out) {
    int t = threadIdx.x;
    double s11 = 0.0, s13 = 0.0, sp = 0.0;
    for (int r = t; r < NROW; r += 1024) {
        float ap1 = g_ap1[r], ap2 = g_ap2[r], an = g_an[r];
        float a1 = g_a1[r], a2 = g_a2[r];
        float y  = (a1 < a2) ? -1.f : 1.f;
        float ym = (a1 == a2) ? 0.f : 1.f;
        float x1 = ap2 * ym;
        float x2 = ap1 * ym + MARGINF * (a1 - a2 - y);
        float t11 = fmaxf(0.f, -y * (x1 - x2) + MARGINF);
        float ap1m = ap1 + MARGINF * (a1 - 1.f);
        float t13 = fmaxf(0.f, -(an - ap1m) + MARGINF);
        s11 += (double)t11; s13 += (double)t13;
        sp += (an > ap1m) ? 1.0 : 0.0;
    }
    __shared__ double r1[1024], r2[1024], r3[1024];
    r1[t] = s11; r2[t] = s13; r3[t] = sp;
    __syncthreads();
    for (int o = 512; o > 0; o >>= 1) {
        if (t < o) { r1[t] += r1[t + o]; r2[t] += r2[t + o]; r3[t] += r3[t + o]; }
        __syncthreads();
    }
    if (t == 0) {
        out[0] = (float)(0.1 * (r1[0] / NROW) + (r2[0] / NROW));
        out[1] = (float)(r3[0] / NROW);
    }
}

// ---------------- launch ----------------
extern "C" void kernel_launch(void* const* d_in, const int* in_sizes, int n_in,
                              void* d_out, int out_size) {
    const float* emb  = (const float*)d_in[0];
    const void*  lab  = d_in[1];
    const float* clot = (const float*)d_in[2];
    float* out = (float*)d_out;

    cudaFuncSetAttribute(k_dist_mma, cudaFuncAttributeMaxDynamicSharedMemorySize, SMEM_TOTAL);

    k_detect<<<1, 1>>>(lab);
    k_prep<<<NROW, 256>>>(emb, clot);
    k_dist_mma<<<NTILE, 256, SMEM_TOTAL>>>(lab);
    k_merge<<<NROW / 256, 256>>>();
    k_alpha<<<NROW / 8, 256>>>(clot);
    k_final<<<1, 1024>>>(out);
}

// round 7
// speedup vs baseline: 8.4615x; 1.1373x over previous
#include <cuda_runtime.h>
#include <cuda_fp16.h>
#include <math.h>
#include <stdint.h>

#define NROW 8192
#define DIM 1024
#define DIM2 512
#define BM 128
#define BN 128
#define NCT (NROW / BN)            // 64 partial slots
#define NTILE 2080                 // 64*65/2 upper-triangle tiles
#define NOFFD 2016                 // strictly-upper tiles
#define BIGF 9999999.0f
#define MARGINF 0.3f

#define STAGE_BYTES 24576          // A hi (128x64B) + B hi|lo (128x128B)
#define B_OFF 8192
#define NSTG 4
#define SMEM_TOTAL (NSTG * STAGE_BYTES)   // 96 KB
#define NSTAGES_K 32               // 1024 / 32

// ---------------- device scratch ----------------
__device__ int   g_lab64;
__device__ float g_sq[NROW];
__device__ float g_nrm[NROW];
__device__ __half g_hi[(size_t)NROW * DIM];
__device__ __half g_lo[(size_t)NROW * DIM];
__device__ float g_p1v[NCT][NROW];
__device__ float g_p2v[NCT][NROW];
__device__ int   g_p1i[NCT][NROW];
__device__ int   g_p2i[NCT][NROW];
__device__ float g_pmn[NCT][NROW];
__device__ float g_ap1[NROW], g_ap2[NROW], g_an[NROW];
__device__ int   g_j1[NROW], g_j2[NROW];
__device__ float g_a1[NROW], g_a2[NROW];

// ---------------- helpers ----------------
__device__ __forceinline__ uint32_t smem_u32(const void* p) {
    uint32_t a;
    asm("{ .reg .u64 t; cvta.to.shared.u64 t, %1; cvt.u32.u64 %0, t; }" : "=r"(a) : "l"(p));
    return a;
}
__device__ __forceinline__ void cpasync16(uint32_t dst, const void* src) {
    asm volatile("cp.async.cg.shared.global [%0], [%1], 16;" :: "r"(dst), "l"(src));
}
#define CP_COMMIT() asm volatile("cp.async.commit_group;" ::: "memory")
#define CP_WAIT2()  asm volatile("cp.async.wait_group 2;" ::: "memory")
#define CP_WAIT0()  asm volatile("cp.async.wait_group 0;" ::: "memory")

#define LDM4(r, addr) \
    asm volatile("ldmatrix.sync.aligned.m8n8.x4.shared.b16 {%0,%1,%2,%3}, [%4];" \
        : "=r"((r)[0]), "=r"((r)[1]), "=r"((r)[2]), "=r"((r)[3]) : "r"(addr))

#define MMA16816(c, a, b0_, b1_) \
    asm volatile("mma.sync.aligned.m16n8k16.row.col.f32.f16.f16.f32 " \
        "{%0,%1,%2,%3}, {%4,%5,%6,%7}, {%8,%9}, {%0,%1,%2,%3};" \
        : "+f"((c)[0]), "+f"((c)[1]), "+f"((c)[2]), "+f"((c)[3]) \
        : "r"((a)[0]), "r"((a)[1]), "r"((a)[2]), "r"((a)[3]), "r"(b0_), "r"(b1_))

__device__ __forceinline__ int getlab(const void* lab, int i, int is64) {
    if (is64) return (int)((const long long*)lab)[i];
    return ((const int*)lab)[i];
}
__device__ __forceinline__ bool keybetter(float av, int ai, float bv, int bi) {
    return (av > bv) || (av == bv && ai < bi);
}
__device__ __forceinline__ uint32_t sw64(uint32_t off)  { return off ^ ((off >> 3) & 0x30u); }
__device__ __forceinline__ uint32_t sw128(uint32_t off) { return off ^ ((off >> 3) & 0x70u); }

__device__ __forceinline__ void merge2(float& v1, int& i1, float& v2, int& i2,
                                       float o1v, int o1i, float o2v, int o2i) {
    if (keybetter(o1v, o1i, v1, i1)) {
        if (keybetter(v1, i1, o2v, o2i)) { v2 = v1; i2 = i1; }
        else                             { v2 = o2v; i2 = o2i; }
        v1 = o1v; i1 = o1i;
    } else if (keybetter(o1v, o1i, v2, i2)) { v2 = o1v; i2 = o1i; }
}

// ---------------- kernel 0: label width detect ----------------
__global__ void k_detect(const void* lab) {
    const unsigned* p = (const unsigned*)lab;
    int is64 = 1;
    for (int i = 0; i < 64; i++) if (p[2 * i + 1] != 0u) { is64 = 0; break; }
    g_lab64 = is64;
}

// ---------------- kernel 1: fused norms + fp16 hi/lo split ----------------
__global__ void k_prep(const float* __restrict__ emb, const float* __restrict__ clot) {
    int r = blockIdx.x, t = threadIdx.x;
    float4 v = ((const float4*)(emb + (size_t)r * DIM))[t];
    float vv[4] = {v.x, v.y, v.z, v.w};
    float s = v.x * v.x + v.y * v.y + v.z * v.z + v.w * v.w;
    __half h[4], l[4];
    #pragma unroll
    for (int i = 0; i < 4; i++) {
        h[i] = __float2half(vv[i]);
        l[i] = __float2half(vv[i] - __half2float(h[i]));
    }
    size_t o = (size_t)r * DIM + t * 4;
    *(__half2*)(g_hi + o)     = __half2(h[0], h[1]);
    *(__half2*)(g_hi + o + 2) = __half2(h[2], h[3]);
    *(__half2*)(g_lo + o)     = __half2(l[0], l[1]);
    *(__half2*)(g_lo + o + 2) = __half2(l[2], l[3]);
    float c = 0.f;
    if (t < DIM2 / 4) {
        float4 w = ((const float4*)(clot + (size_t)r * DIM2))[t];
        c = w.x * w.x + w.y * w.y + w.z * w.z + w.w * w.w;
    }
    __shared__ float se[256], sc[256];
    se[t] = s; sc[t] = c;
    __syncthreads();
    for (int o2 = 128; o2 > 0; o2 >>= 1) { if (t < o2) { se[t] += se[t + o2]; sc[t] += sc[t + o2]; } __syncthreads(); }
    if (t == 0) { g_sq[r] = se[0]; g_nrm[r] = sqrtf(sc[0]); }
}

// ---------------- kernel 2: fp16 2-pass HMMA GEMM, upper-triangle tiles ----------------
// selection in d^2 domain (sqrt deferred to k_merge); diagonal tiles mapped last.
__global__ __launch_bounds__(256, 2) void k_dist_mma(const void* __restrict__ lab) {
    extern __shared__ char smem[];
    const uint32_t sb = smem_u32(smem);
    const int tid = threadIdx.x;
    const int lane = tid & 31, wid = tid >> 5;
    const int wm = wid >> 2, wn = wid & 3;
    const int lab64 = g_lab64;

    // tile id -> (rb, cb): ids [0,2016) strictly-upper, [2016,2080) diagonal (run last)
    int rb, cb;
    if (blockIdx.x < NOFFD) {
        int u = blockIdx.x; rb = 0;
        while (u >= 63 - rb) { u -= 63 - rb; rb++; }
        cb = rb + 1 + u;
    } else {
        rb = cb = blockIdx.x - NOFFD;
    }
    const int r0 = rb * BM, c0 = cb * BN;

    // ---- per-thread cp.async descriptors (6 x 16B per stage) ----
    const char* srcp[6];
    uint32_t dsto[6];
    #pragma unroll
    for (int v = 0; v < 2; v++) {          // A hi: 512 ops
        int i = tid + v * 256;
        int row = i >> 2, seg = i & 3;
        srcp[v] = (const char*)(g_hi + (size_t)(r0 + row) * DIM + seg * 8);
        dsto[v] = sw64((uint32_t)row * 64u + (uint32_t)seg * 16u);
    }
    #pragma unroll
    for (int v = 2; v < 6; v++) {          // B hi|lo: 1024 ops
        int j = tid + (v - 2) * 256;
        int row = j >> 3, seg = j & 7;
        const __half* sbase = (seg < 4) ? g_hi : g_lo;
        srcp[v] = (const char*)(sbase + (size_t)(c0 + row) * DIM + (seg & 3) * 8);
        dsto[v] = B_OFF + sw128((uint32_t)row * 128u + (uint32_t)seg * 16u);
    }

    // ---- ldmatrix pre-offsets + row-dependent swizzle masks ----
    uint32_t preA[4], mskA[4], preB[2], mskB[2];
    {
        int rA = wm * 64 + (lane & 15);
        int sA = lane >> 4;
        #pragma unroll
        for (int mt = 0; mt < 4; mt++) {
            uint32_t p = (uint32_t)(rA + mt * 16) * 64u + (uint32_t)sA * 16u;
            mskA[mt] = (p >> 3) & 0x30u;
            preA[mt] = p;
        }
        int rB = wn * 32 + ((lane >> 4) << 3) + (lane & 7);
        int sB = (lane >> 3) & 1;
        #pragma unroll
        for (int np = 0; np < 2; np++) {
            uint32_t p = (uint32_t)(rB + np * 16) * 128u + (uint32_t)sB * 16u;
            mskB[np] = (p >> 3) & 0x70u;
            preB[np] = p;
        }
    }

    float acc[4][4][4];
    #pragma unroll
    for (int a = 0; a < 4; a++)
        #pragma unroll
        for (int b = 0; b < 4; b++)
            #pragma unroll
            for (int c = 0; c < 4; c++) acc[a][b][c] = 0.f;

    // ---- prologue: fill 3 stages ----
    #pragma unroll
    for (int p = 0; p < 3; p++) {
        uint32_t db = sb + (uint32_t)p * STAGE_BYTES;
        #pragma unroll
        for (int v = 0; v < 6; v++) cpasync16(db + dsto[v], srcp[v] + (size_t)p * 64);
        CP_COMMIT();
    }

    // ---- main loop: 32 K-stages of 32 ----
    for (int s = 0; s < NSTAGES_K; s++) {
        CP_WAIT2();
        __syncthreads();
        {
            int sn = s + 3;
            if (sn < NSTAGES_K) {
                uint32_t db = sb + (uint32_t)(sn & 3) * STAGE_BYTES;
                #pragma unroll
                for (int v = 0; v < 6; v++) cpasync16(db + dsto[v], srcp[v] + (size_t)sn * 64);
            }
            CP_COMMIT();
        }
        const uint32_t base = sb + (uint32_t)(s & 3) * STAGE_BYTES;
        const uint32_t baseB = base + B_OFF;

        #pragma unroll
        for (int kc = 0; kc < 2; kc++) {
            const uint32_t kd = (uint32_t)kc * 32u;
            uint32_t BH[2][4], BL[2][4];
            #pragma unroll
            for (int np = 0; np < 2; np++) {
                LDM4(BH[np], baseB + ((preB[np] + kd) ^ mskB[np]));
                LDM4(BL[np], baseB + ((preB[np] + kd + 64u) ^ mskB[np]));
            }
            uint32_t AH[4][4];
            #pragma unroll
            for (int mt = 0; mt < 4; mt++) LDM4(AH[mt], base + ((preA[mt] + kd) ^ mskA[mt]));
            #pragma unroll
            for (int mt = 0; mt < 4; mt++) {
                #pragma unroll
                for (int nt = 0; nt < 4; nt++)
                    MMA16816(acc[mt][nt], AH[mt], BH[nt >> 1][(nt & 1) * 2], BH[nt >> 1][(nt & 1) * 2 + 1]);
                #pragma unroll
                for (int nt = 0; nt < 4; nt++)
                    MMA16816(acc[mt][nt], AH[mt], BL[nt >> 1][(nt & 1) * 2], BL[nt >> 1][(nt & 1) * 2 + 1]);
            }
        }
    }
    CP_WAIT0();
    __syncthreads();   // stages dead; smem reused below

    const int tg = lane & 3, g = lane >> 2;
    float sqj[8]; int labj[8];
    #pragma unroll
    for (int ln = 0; ln < 8; ln++) {
        int cc = c0 + wn * 32 + (ln >> 1) * 8 + tg * 2 + (ln & 1);
        sqj[ln] = g_sq[cc];
        labj[ln] = getlab(lab, cc, lab64);
    }
    float sqi[8]; int labi[8];
    #pragma unroll
    for (int lm = 0; lm < 8; lm++) {
        int m = r0 + wm * 64 + (lm >> 1) * 16 + g + (lm & 1) * 8;
        sqi[lm] = g_sq[m];
        labi[lm] = getlab(lab, m, lab64);
    }

    // smem overlays
    float* sv1 = (float*)smem;              // [128][4]
    float* sv2 = (float*)(smem + 2048);
    float* smn = (float*)(smem + 4096);
    int*   si1 = (int*)(smem + 6144);
    int*   si2 = (int*)(smem + 8192);
    float* cv1 = (float*)(smem + 16384);    // [128][2]
    float* cv2 = (float*)(smem + 17408);
    float* cmn = (float*)(smem + 18432);
    int*   ci1 = (int*)(smem + 19456);
    int*   ci2 = (int*)(smem + 20480);

    // ======== row stats (d^2 domain) ========
    {
        float b1v[8], b2v[8], mnv[8]; int b1i[8], b2i[8];
        #pragma unroll
        for (int lm = 0; lm < 8; lm++) {
            float v1 = -INFINITY, v2 = -INFINITY, mn = INFINITY;
            int i1 = 0x7fffffff, i2 = 0x7fffffff;
            #pragma unroll
            for (int ln = 0; ln < 8; ln++) {
                int col = c0 + wn * 32 + (ln >> 1) * 8 + tg * 2 + (ln & 1);
                float dot = acc[lm >> 1][ln >> 1][(lm & 1) * 2 + (ln & 1)];
                float d2 = sqi[lm] + sqj[ln] - 2.0f * dot;
                bool same = (labi[lm] == labj[ln]);
                float pv = same ? d2 : d2 - BIGF;
                float nv = same ? d2 + BIGF : d2;
                mn = fminf(mn, nv);
                if (keybetter(pv, col, v1, i1)) { v2 = v1; i2 = i1; v1 = pv; i1 = col; }
                else if (keybetter(pv, col, v2, i2)) { v2 = pv; i2 = col; }
            }
            b1v[lm] = v1; b1i[lm] = i1; b2v[lm] = v2; b2i[lm] = i2; mnv[lm] = mn;
        }
        #pragma unroll
        for (int lm = 0; lm < 8; lm++) {
            #pragma unroll
            for (int off = 1; off <= 2; off <<= 1) {
                float o1v = __shfl_xor_sync(0xffffffffu, b1v[lm], off);
                int   o1i = __shfl_xor_sync(0xffffffffu, b1i[lm], off);
                float o2v = __shfl_xor_sync(0xffffffffu, b2v[lm], off);
                int   o2i = __shfl_xor_sync(0xffffffffu, b2i[lm], off);
                float omn = __shfl_xor_sync(0xffffffffu, mnv[lm], off);
                mnv[lm] = fminf(mnv[lm], omn);
                merge2(b1v[lm], b1i[lm], b2v[lm], b2i[lm], o1v, o1i, o2v, o2i);
            }
        }
        if (tg == 0) {
            #pragma unroll
            for (int lm = 0; lm < 8; lm++) {
                int rl = wm * 64 + (lm >> 1) * 16 + g + (lm & 1) * 8;
                sv1[rl * 4 + wn] = b1v[lm]; si1[rl * 4 + wn] = b1i[lm];
                sv2[rl * 4 + wn] = b2v[lm]; si2[rl * 4 + wn] = b2i[lm];
                smn[rl * 4 + wn] = mnv[lm];
            }
        }
    }

    // ======== col stats (transposed harvest; skip on diagonal) ========
    if (rb != cb) {
        float b1v[8], b2v[8], mnv[8]; int b1i[8], b2i[8];
        #pragma unroll
        for (int ln = 0; ln < 8; ln++) {
            float v1 = -INFINITY, v2 = -INFINITY, mn = INFINITY;
            int i1 = 0x7fffffff, i2 = 0x7fffffff;
            #pragma unroll
            for (int lm = 0; lm < 8; lm++) {
                int rowidx = r0 + wm * 64 + (lm >> 1) * 16 + g + (lm & 1) * 8;
                float dot = acc[lm >> 1][ln >> 1][(lm & 1) * 2 + (ln & 1)];
                float d2 = sqi[lm] + sqj[ln] - 2.0f * dot;
                bool same = (labi[lm] == labj[ln]);
                float pv = same ? d2 : d2 - BIGF;
                float nv = same ? d2 + BIGF : d2;
                mn = fminf(mn, nv);
                if (keybetter(pv, rowidx, v1, i1)) { v2 = v1; i2 = i1; v1 = pv; i1 = rowidx; }
                else if (keybetter(pv, rowidx, v2, i2)) { v2 = pv; i2 = rowidx; }
            }
            b1v[ln] = v1; b1i[ln] = i1; b2v[ln] = v2; b2i[ln] = i2; mnv[ln] = mn;
        }
        #pragma unroll
        for (int ln = 0; ln < 8; ln++) {
            #pragma unroll
            for (int off = 4; off <= 16; off <<= 1) {
                float o1v = __shfl_xor_sync(0xffffffffu, b1v[ln], off);
                int   o1i = __shfl_xor_sync(0xffffffffu, b1i[ln], off);
                float o2v = __shfl_xor_sync(0xffffffffu, b2v[ln], off);
                int   o2i = __shfl_xor_sync(0xffffffffu, b2i[ln], off);
                float omn = __shfl_xor_sync(0xffffffffu, mnv[ln], off);
                mnv[ln] = fminf(mnv[ln], omn);
                merge2(b1v[ln], b1i[ln], b2v[ln], b2i[ln], o1v, o1i, o2v, o2i);
            }
        }
        if (g == 0) {
            #pragma unroll
            for (int ln = 0; ln < 8; ln++) {
                int cl = wn * 32 + (ln >> 1) * 8 + tg * 2 + (ln & 1);
                cv1[cl * 2 + wm] = b1v[ln]; ci1[cl * 2 + wm] = b1i[ln];
                cv2[cl * 2 + wm] = b2v[ln]; ci2[cl * 2 + wm] = b2i[ln];
                cmn[cl * 2 + wm] = mnv[ln];
            }
        }
    }
    __syncthreads();

    // final merges + global writes
    if (tid < 128) {
        {
            float v1 = -INFINITY, v2 = -INFINITY, mn = INFINITY;
            int i1 = 0x7fffffff, i2 = 0x7fffffff;
            #pragma unroll
            for (int w = 0; w < 4; w++) {
                mn = fminf(mn, smn[tid * 4 + w]);
                merge2(v1, i1, v2, i2, sv1[tid * 4 + w], si1[tid * 4 + w], sv2[tid * 4 + w], si2[tid * 4 + w]);
            }
            int r = r0 + tid;
            g_p1v[cb][r] = v1; g_p1i[cb][r] = i1;
            g_p2v[cb][r] = v2; g_p2i[cb][r] = i2;
            g_pmn[cb][r] = mn;
        }
        if (rb != cb) {
            float v1 = -INFINITY, v2 = -INFINITY, mn = INFINITY;
            int i1 = 0x7fffffff, i2 = 0x7fffffff;
            #pragma unroll
            for (int w = 0; w < 2; w++) {
                mn = fminf(mn, cmn[tid * 2 + w]);
                merge2(v1, i1, v2, i2, cv1[tid * 2 + w], ci1[tid * 2 + w], cv2[tid * 2 + w], ci2[tid * 2 + w]);
            }
            int r = c0 + tid;
            g_p1v[rb][r] = v1; g_p1i[rb][r] = i1;
            g_p2v[rb][r] = v2; g_p2i[rb][r] = i2;
            g_pmn[rb][r] = mn;
        }
    }
}

// ---------------- kernel 3: warp-per-row merge + d^2 -> dist conversion ----------------
__global__ void k_merge() {
    int t = threadIdx.x;
    int r = blockIdx.x * 8 + (t >> 5);
    int l = t & 31;
    float b1v = g_p1v[l][r]; int b1i = g_p1i[l][r];
    float b2v = g_p2v[l][r]; int b2i = g_p2i[l][r];
    float mn  = g_pmn[l][r];
    int c2 = l + 32;
    mn = fminf(mn, g_pmn[c2][r]);
    merge2(b1v, b1i, b2v, b2i, g_p1v[c2][r], g_p1i[c2][r], g_p2v[c2][r], g_p2i[c2][r]);
    #pragma unroll
    for (int off = 16; off > 0; off >>= 1) {
        float o1v = __shfl_xor_sync(0xffffffffu, b1v, off);
        int   o1i = __shfl_xor_sync(0xffffffffu, b1i, off);
        float o2v = __shfl_xor_sync(0xffffffffu, b2v, off);
        int   o2i = __shfl_xor_sync(0xffffffffu, b2i, off);
        float omn = __shfl_xor_sync(0xffffffffu, mn,  off);
        mn = fminf(mn, omn);
        merge2(b1v, b1i, b2v, b2i, o1v, o1i, o2v, o2i);
    }
    if (l == 0) {
        // convert d^2-domain keys back to dist-domain values
        float ap1 = (b1v < -1e6f) ? (sqrtf(fmaxf(b1v + BIGF, 1e-12f)) - BIGF)
                                  : sqrtf(fmaxf(b1v, 1e-12f));
        float ap2 = (b2v < -1e6f) ? (sqrtf(fmaxf(b2v + BIGF, 1e-12f)) - BIGF)
                                  : sqrtf(fmaxf(b2v, 1e-12f));
        float an  = (mn > 1e6f) ? (sqrtf(fmaxf(mn - BIGF, 1e-12f)) + BIGF)
                                : sqrtf(fmaxf(mn, 1e-12f));
        g_ap1[r] = ap1; g_ap2[r] = ap2; g_an[r] = an;
        g_j1[r] = b1i;  g_j2[r] = b2i;
    }
}

// ---------------- kernel 4: cos at the two selected positives ----------------
__global__ void k_alpha(const float* __restrict__ clot) {
    int w = threadIdx.x >> 5, lane = threadIdx.x & 31;
    int r = blockIdx.x * 8 + w;
    int j1 = g_j1[r], j2 = g_j2[r];
    const float* cr = clot + (size_t)r * DIM2;
    const float* ca = clot + (size_t)j1 * DIM2;
    const float* cb = clot + (size_t)j2 * DIM2;
    float d1 = 0.f, d2 = 0.f;
    for (int k = lane; k < DIM2; k += 32) {
        float c = cr[k];
        d1 = fmaf(c, ca[k], d1);
        d2 = fmaf(c, cb[k], d2);
    }
    for (int o = 16; o > 0; o >>= 1) {
        d1 += __shfl_xor_sync(0xffffffffu, d1, o);
        d2 += __shfl_xor_sync(0xffffffffu, d2, o);
    }
    if (lane == 0) {
        g_a1[r] = d1 / (g_nrm[r] * g_nrm[j1]);
        g_a2[r] = d2 / (g_nrm[r] * g_nrm[j2]);
    }
}

// ---------------- kernel 5: final loss reduction ----------------
__global__ void k_final(float* __restrict__ out) {
    int t = threadIdx.x;
    double s11 = 0.0, s13 = 0.0, sp = 0.0;
    for (int r = t; r < NROW; r += 1024) {
        float ap1 = g_ap1[r], ap2 = g_ap2[r], an = g_an[r];
        float a1 = g_a1[r], a2 = g_a2[r];
        float y  = (a1 < a2) ? -1.f : 1.f;
        float ym = (a1 == a2) ? 0.f : 1.f;
        float x1 = ap2 * ym;
        float x2 = ap1 * ym + MARGINF * (a1 - a2 - y);
        float t11 = fmaxf(0.f, -y * (x1 - x2) + MARGINF);
        float ap1m = ap1 + MARGINF * (a1 - 1.f);
        float t13 = fmaxf(0.f, -(an - ap1m) + MARGINF);
        s11 += (double)t11; s13 += (double)t13;
        sp += (an > ap1m) ? 1.0 : 0.0;
    }
    __shared__ double r1[1024], r2[1024], r3[1024];
    r1[t] = s11; r2[t] = s13; r3[t] = sp;
    __syncthreads();
    for (int o = 512; o > 0; o >>= 1) {
        if (t < o) { r1[t] += r1[t + o]; r2[t] += r2[t + o]; r3[t] += r3[t + o]; }
        __syncthreads();
    }
    if (t == 0) {
        out[0] = (float)(0.1 * (r1[0] / NROW) + (r2[0] / NROW));
        out[1] = (float)(r3[0] / NROW);
    }
}

// ---------------- launch ----------------
extern "C" void kernel_launch(void* const* d_in, const int* in_sizes, int n_in,
                              void* d_out, int out_size) {
    const float* emb  = (const float*)d_in[0];
    const void*  lab  = d_in[1];
    const float* clot = (const float*)d_in[2];
    float* out = (float*)d_out;

    cudaFuncSetAttribute(k_dist_mma, cudaFuncAttributeMaxDynamicSharedMemorySize, SMEM_TOTAL);

    k_detect<<<1, 1>>>(lab);
    k_prep<<<NROW, 256>>>(emb, clot);
    k_dist_mma<<<NTILE, 256, SMEM_TOTAL>>>(lab);
    k_merge<<<NROW / 8, 256>>>();
    k_alpha<<<NROW / 8, 256>>>(clot);
    k_final<<<1, 1024>>>(out);
}